// round 3
// baseline (speedup 1.0000x reference)
#include <cuda_runtime.h>
#include <math.h>

#define NN 60000
#define NE 240000
#define NR 4
#define NG 128
#define DIN 768
#define DH 256
#define NL 6

// ---------------- scratch (static device globals; no allocation) ----------------
__device__ __align__(16) float g_h[(size_t)NN * DH];          // current activations
__device__ __align__(16) float g_acc[(size_t)NN * DH];        // root transform + edge accumulation
__device__ __align__(16) float g_y[(size_t)NR * NN * DH];     // per-relation transformed features
__device__ __align__(16) float g_cnt[NR * NN];
__device__ __align__(16) float g_invcnt[NR * NN];
__device__ __align__(16) float g_psum[NG * DH];
__device__ __align__(16) int   g_pmax[NG * DH];
__device__ __align__(16) float g_gcnt[NG];

// decoded int32 index arrays + dtype flags
__device__ int g_src[NE];
__device__ int g_dst[NE];
__device__ int g_rel[NE];
__device__ int g_bat[NN];
__device__ int g_is64_ei, g_is64_ea, g_is64_b;

// ---------------- dtype detection ----------------
// For a buffer of nonnegative small int64 values (little-endian), every u32 word
// at an odd position is 0. For int32 data, strided samples across the full range
// are essentially surely nonzero somewhere. One block, 256 threads.
__global__ void detect_kernel(const unsigned* __restrict__ ei,
                              const unsigned* __restrict__ ea,
                              const unsigned* __restrict__ ba) {
    __shared__ int s[3];
    int t = threadIdx.x;
    if (t < 3) s[t] = 1;
    __syncthreads();
    // edge_index: int32 words = 2*NE = 480000; sample k*937 pairs (max word 478-odd)
    { unsigned w = ei[2 * (t * 937) + 1]; if (w != 0) atomicAnd(&s[0], 0); }
    // edge_attr: int32 words = NE = 240000; sample k*468
    { unsigned w = ea[2 * (t * 468) + 1]; if (w != 0) atomicAnd(&s[1], 0); }
    // batch: int32 words = NN = 60000; sample k*117 (sorted data -> must stride whole range)
    { unsigned w = ba[2 * (t * 117) + 1]; if (w != 0) atomicAnd(&s[2], 0); }
    __syncthreads();
    if (t == 0) { g_is64_ei = s[0]; g_is64_ea = s[1]; g_is64_b = s[2]; }
}

// ---------------- decode indices to int32 with clamps (trap-proof) ----------------
__global__ void cvt_edges_kernel(const void* __restrict__ ei, const void* __restrict__ ea) {
    int e = blockIdx.x * blockDim.x + threadIdx.x;
    if (e >= NE) return;
    long long s, d, r;
    if (g_is64_ei) {
        const long long* p = (const long long*)ei;
        s = p[e]; d = p[NE + e];
    } else {
        const int* p = (const int*)ei;
        s = p[e]; d = p[NE + e];
    }
    if (g_is64_ea) r = ((const long long*)ea)[e];
    else           r = ((const int*)ea)[e];
    g_src[e] = (int)(s < 0 ? 0 : (s >= NN ? NN - 1 : s));
    g_dst[e] = (int)(d < 0 ? 0 : (d >= NN ? NN - 1 : d));
    g_rel[e] = (int)(r & 3);
}

__global__ void cvt_batch_kernel(const void* __restrict__ ba) {
    int i = blockIdx.x * blockDim.x + threadIdx.x;
    if (i >= NN) return;
    long long b = g_is64_b ? ((const long long*)ba)[i] : (long long)((const int*)ba)[i];
    g_bat[i] = (int)(b < 0 ? 0 : (b >= NG ? NG - 1 : b));
}

// ---------------- small utility kernels ----------------
__global__ void zero_cnt_kernel() {
    int i = blockIdx.x * blockDim.x + threadIdx.x;
    if (i < NR * NN) g_cnt[i] = 0.f;
}

__global__ void count_edges_kernel() {
    int e = blockIdx.x * blockDim.x + threadIdx.x;
    if (e >= NE) return;
    atomicAdd(&g_cnt[g_rel[e] * NN + g_dst[e]], 1.f);
}

__global__ void make_inv_kernel() {
    int i = blockIdx.x * blockDim.x + threadIdx.x;
    if (i < NR * NN) g_invcnt[i] = 1.f / fmaxf(g_cnt[i], 1.f);
}

__global__ void zero_pool_kernel() {
    int i = blockIdx.x * blockDim.x + threadIdx.x;
    if (i < NG * DH) { g_psum[i] = 0.f; g_pmax[i] = 0; }
    if (i < NG) g_gcnt[i] = 0.f;
}

// ---------------- fused GEMM: C[60000 x 1280] = A[60000 x K] @ [W_0|W_1|W_2|W_3|root] ----------------
// A == nullptr means "use g_h". Virtual cols [0,1024) -> g_y, [1024,1280) -> g_acc (+bias).
#define BM 128
#define BN 128
#define BK 16

__global__ __launch_bounds__(256) void gemm_fused(
    const float* __restrict__ A, const float* __restrict__ W,
    const float* __restrict__ root, const float* __restrict__ bias, int K)
{
    __shared__ float As[BK][BM];
    __shared__ float Bs[BK][BN];

    const float* __restrict__ Ap = A ? A : (const float*)g_h;

    const int bm = blockIdx.x * BM;
    const int cn = blockIdx.y * BN;                 // virtual col base, multiple of 128
    const bool isRoot = (cn >= NR * DH);
    const float* Bp = isRoot ? (root + (cn - NR * DH))
                             : (W + (size_t)(cn >> 8) * K * DH + (cn & (DH - 1)));

    const int tid  = threadIdx.x;
    const int tx   = tid & 15;
    const int ty   = tid >> 4;
    const int arow = tid >> 2;          // 0..63
    const int acol = (tid & 3) * 4;     // 0,4,8,12
    const int brow = tid >> 5;          // 0..7
    const int bcol = (tid & 31) * 4;    // 0..124

    float acc[8][8];
    #pragma unroll
    for (int i = 0; i < 8; i++)
        #pragma unroll
        for (int j = 0; j < 8; j++) acc[i][j] = 0.f;

    for (int k0 = 0; k0 < K; k0 += BK) {
        #pragma unroll
        for (int i = 0; i < 2; i++) {
            int r  = arow + i * 64;
            int gr = bm + r;
            float4 v = make_float4(0.f, 0.f, 0.f, 0.f);
            if (gr < NN) v = *(const float4*)&Ap[(size_t)gr * K + k0 + acol];
            As[acol + 0][r] = v.x;
            As[acol + 1][r] = v.y;
            As[acol + 2][r] = v.z;
            As[acol + 3][r] = v.w;
        }
        #pragma unroll
        for (int i = 0; i < 2; i++) {
            int kr = brow + i * 8;
            float4 v = *(const float4*)&Bp[(size_t)(k0 + kr) * DH + bcol];
            *(float4*)&Bs[kr][bcol] = v;
        }
        __syncthreads();

        #pragma unroll
        for (int k = 0; k < BK; k++) {
            float4 a0 = *(const float4*)&As[k][ty * 8];
            float4 a1 = *(const float4*)&As[k][ty * 8 + 4];
            float4 b0 = *(const float4*)&Bs[k][tx * 8];
            float4 b1 = *(const float4*)&Bs[k][tx * 8 + 4];
            float av[8] = {a0.x, a0.y, a0.z, a0.w, a1.x, a1.y, a1.z, a1.w};
            float bv[8] = {b0.x, b0.y, b0.z, b0.w, b1.x, b1.y, b1.z, b1.w};
            #pragma unroll
            for (int i = 0; i < 8; i++)
                #pragma unroll
                for (int j = 0; j < 8; j++)
                    acc[i][j] += av[i] * bv[j];
        }
        __syncthreads();
    }

    if (isRoot) {
        int cb = cn - NR * DH;   // 0 or 128
        #pragma unroll
        for (int i = 0; i < 8; i++) {
            int r = bm + ty * 8 + i;
            if (r >= NN) break;
            #pragma unroll
            for (int j = 0; j < 8; j++) {
                int c = cb + tx * 8 + j;
                g_acc[(size_t)r * DH + c] = acc[i][j] + bias[c];
            }
        }
    } else {
        int rel = cn >> 8;
        int cb  = cn & (DH - 1);
        float* yb = g_y + (size_t)rel * NN * DH;
        #pragma unroll
        for (int i = 0; i < 8; i++) {
            int r = bm + ty * 8 + i;
            if (r >= NN) break;
            #pragma unroll
            for (int j = 0; j < 8; j++)
                yb[(size_t)r * DH + cb + tx * 8 + j] = acc[i][j];
        }
    }
}

// ---------------- edge scatter: acc[dst] += y[rel][src] * invcnt[rel][dst] ----------------
__global__ __launch_bounds__(256) void edge_scatter() {
    int e = blockIdx.x * 8 + (threadIdx.x >> 5);
    if (e >= NE) return;
    int lane = threadIdx.x & 31;
    int src = g_src[e];
    int dst = g_dst[e];
    int rel = g_rel[e];
    float inv = g_invcnt[rel * NN + dst];
    const float4* ys = (const float4*)(g_y + ((size_t)rel * NN + src) * DH);
    float* ad = g_acc + (size_t)dst * DH;
    #pragma unroll
    for (int i = 0; i < 2; i++) {
        float4 v = ys[lane + 32 * i];
        int base = (lane + 32 * i) * 4;
        atomicAdd(&ad[base + 0], v.x * inv);
        atomicAdd(&ad[base + 1], v.y * inv);
        atomicAdd(&ad[base + 2], v.z * inv);
        atomicAdd(&ad[base + 3], v.w * inv);
    }
}

// ---------------- relu: g_h = relu(g_acc) ----------------
__global__ void relu_kernel() {
    int i = blockIdx.x * blockDim.x + threadIdx.x;
    const int n4 = NN * DH / 4;
    if (i < n4) {
        float4 v = ((const float4*)g_acc)[i];
        v.x = fmaxf(v.x, 0.f);
        v.y = fmaxf(v.y, 0.f);
        v.z = fmaxf(v.z, 0.f);
        v.w = fmaxf(v.w, 0.f);
        ((float4*)g_h)[i] = v;
    }
}

// ---------------- graph pooling (sum + max + count) ----------------
__global__ void pool_kernel() {
    int idx = blockIdx.x * blockDim.x + threadIdx.x;
    if (idx >= NN * DH) return;
    int node = idx >> 8;
    int d    = idx & (DH - 1);
    int g    = g_bat[node];
    float v  = g_h[idx];
    atomicAdd(&g_psum[g * DH + d], v);
    atomicMax(&g_pmax[g * DH + d], __float_as_int(v));  // v >= 0 post-relu -> int-order ok
    if (d == 0) atomicAdd(&g_gcnt[g], 1.f);
}

// ---------------- final MLP head: [512] -> 128 -> 1 -> sigmoid ----------------
__global__ __launch_bounds__(128) void mlp_kernel(
    const float* __restrict__ fc1w, const float* __restrict__ fc1b,
    const float* __restrict__ fc2w, const float* __restrict__ fc2b,
    float* __restrict__ out)
{
    __shared__ float gv[2 * DH];
    __shared__ float partial[4];
    int gi = blockIdx.x;
    int t  = threadIdx.x;
    float cnt = fmaxf(g_gcnt[gi], 1.f);
    for (int i = t; i < DH; i += 128) {
        gv[i]      = g_psum[gi * DH + i] / cnt;
        gv[DH + i] = __int_as_float(g_pmax[gi * DH + i]);
    }
    __syncthreads();
    float a = fc1b[t];
    #pragma unroll 8
    for (int i = 0; i < 2 * DH; i++) a += gv[i] * fc1w[i * 128 + t];
    a = fmaxf(a, 0.f);
    float p = a * fc2w[t];
    #pragma unroll
    for (int o = 16; o > 0; o >>= 1) p += __shfl_down_sync(0xffffffffu, p, o);
    if ((t & 31) == 0) partial[t >> 5] = p;
    __syncthreads();
    if (t == 0) {
        float s = partial[0] + partial[1] + partial[2] + partial[3] + fc2b[0];
        out[gi] = 1.f / (1.f + expf(-s));
    }
}

// ---------------- launch ----------------
extern "C" void kernel_launch(void* const* d_in, const int* in_sizes, int n_in,
                              void* d_out, int out_size)
{
    const float* x         = (const float*)d_in[0];
    const void*  ei        = d_in[1];
    const void*  ea        = d_in[2];
    const void*  ba        = d_in[3];
    const float* w0        = (const float*)d_in[4];
    const float* root0     = (const float*)d_in[5];
    const float* b0        = (const float*)d_in[6];
    const float* w_rest    = (const float*)d_in[7];
    const float* root_rest = (const float*)d_in[8];
    const float* b_rest    = (const float*)d_in[9];
    const float* fc1w      = (const float*)d_in[10];
    const float* fc1b      = (const float*)d_in[11];
    const float* fc2w      = (const float*)d_in[12];
    const float* fc2b      = (const float*)d_in[13];
    float* out = (float*)d_out;

    const int T = 256;

    // detect int32-vs-int64 index dtypes, then decode into int32 scratch
    detect_kernel<<<1, 256>>>((const unsigned*)ei, (const unsigned*)ea, (const unsigned*)ba);
    cvt_edges_kernel<<<(NE + T - 1) / T, T>>>(ei, ea);
    cvt_batch_kernel<<<(NN + T - 1) / T, T>>>(ba);

    // per-(relation,dst) mean normalizers
    zero_cnt_kernel<<<(NR * NN + T - 1) / T, T>>>();
    count_edges_kernel<<<(NE + T - 1) / T, T>>>();
    make_inv_kernel<<<(NR * NN + T - 1) / T, T>>>();

    dim3 ggrid((NN + BM - 1) / BM, (NR * DH + DH) / BN);   // 469 x 10
    const int egrid = (NE + 7) / 8;
    const int rgrid = (NN * DH / 4 + T - 1) / T;

    // layer 0 (K = 768)
    gemm_fused<<<ggrid, 256>>>(x, w0, root0, b0, DIN);
    edge_scatter<<<egrid, 256>>>();
    relu_kernel<<<rgrid, T>>>();

    // layers 1..5 (K = 256)
    for (int l = 0; l < NL - 1; l++) {
        const float* W  = w_rest    + (size_t)l * NR * DH * DH;
        const float* Rt = root_rest + (size_t)l * DH * DH;
        const float* B  = b_rest    + (size_t)l * DH;
        gemm_fused<<<ggrid, 256>>>(nullptr, W, Rt, B, DH);
        edge_scatter<<<egrid, 256>>>();
        relu_kernel<<<rgrid, T>>>();
    }

    // pooling + head
    zero_pool_kernel<<<(NG * DH + T - 1) / T, T>>>();
    pool_kernel<<<(NN * DH + T - 1) / T, T>>>();
    mlp_kernel<<<NG, 128>>>(fc1w, fc1b, fc2w, fc2b, out);
}

// round 7
// speedup vs baseline: 1.9510x; 1.9510x over previous
#include <cuda_runtime.h>
#include <cuda_bf16.h>
#include <math.h>
#include <stdint.h>

#define NN 60000
#define NNP 60128          // padded rows (tile overrun safe)
#define NE 240000
#define NR 4
#define NG 128
#define DIN 768
#define DH 256
#define NL 6

// ---------------- scratch (static device globals; no allocation) ----------------
__device__ __align__(16) float g_h[(size_t)NN * DH];          // fp32 activations (for pooling)
__device__ __align__(16) float g_acc[(size_t)NN * DH];        // root transform + edge accumulation
__device__ __align__(16) float g_y[(size_t)NR * NN * DH];     // per-relation transformed features
__device__ __align__(16) float g_cnt[NR * NN];
__device__ __align__(16) float g_invcnt[NR * NN];
__device__ __align__(16) float g_psum[NG * DH];
__device__ __align__(16) int   g_pmax[NG * DH];
__device__ __align__(16) float g_gcnt[NG];

// bf16 hi/lo split inputs for tensor-core GEMMs
__device__ __align__(16) __nv_bfloat16 g_xh[(size_t)NNP * DIN];
__device__ __align__(16) __nv_bfloat16 g_xl[(size_t)NNP * DIN];
__device__ __align__(16) __nv_bfloat16 g_hbh[(size_t)NNP * DH];
__device__ __align__(16) __nv_bfloat16 g_hbl[(size_t)NNP * DH];
// transposed weights: layer0 [1280][768] then layers1-5 [1280][256] each
#define W0_ELEMS (1280 * 768)
#define WR_ELEMS (1280 * 256)
#define WT_TOTAL (W0_ELEMS + 5 * WR_ELEMS)
__device__ __align__(16) __nv_bfloat16 g_wth[WT_TOTAL];
__device__ __align__(16) __nv_bfloat16 g_wtl[WT_TOTAL];

// decoded int32 index arrays + dtype flags
__device__ int g_src[NE];
__device__ int g_dst[NE];
__device__ int g_rel[NE];
__device__ int g_bat[NN];
__device__ int g_is64_ei, g_is64_ea, g_is64_b;

// ---------------- helpers ----------------
__device__ __forceinline__ uint32_t smem_to_u32(const void* p) {
    uint32_t a;
    asm("{ .reg .u64 t; cvta.to.shared.u64 t, %1; cvt.u32.u64 %0, t; }" : "=r"(a) : "l"(p));
    return a;
}

__device__ __forceinline__ void ldsm4(uint32_t& r0, uint32_t& r1, uint32_t& r2, uint32_t& r3, uint32_t addr) {
    asm volatile("ldmatrix.sync.aligned.m8n8.x4.shared.b16 {%0,%1,%2,%3}, [%4];"
                 : "=r"(r0), "=r"(r1), "=r"(r2), "=r"(r3) : "r"(addr));
}

__device__ __forceinline__ void mma16816(float* d, const uint32_t* a, uint32_t b0, uint32_t b1) {
    asm volatile("mma.sync.aligned.m16n8k16.row.col.f32.bf16.bf16.f32 "
                 "{%0,%1,%2,%3}, {%4,%5,%6,%7}, {%8,%9}, {%0,%1,%2,%3};"
                 : "+f"(d[0]), "+f"(d[1]), "+f"(d[2]), "+f"(d[3])
                 : "r"(a[0]), "r"(a[1]), "r"(a[2]), "r"(a[3]), "r"(b0), "r"(b1));
}

// ---------------- dtype detection ----------------
__global__ void detect_kernel(const unsigned* __restrict__ ei,
                              const unsigned* __restrict__ ea,
                              const unsigned* __restrict__ ba) {
    __shared__ int s[3];
    int t = threadIdx.x;
    if (t < 3) s[t] = 1;
    __syncthreads();
    { unsigned w = ei[2 * (t * 937) + 1]; if (w != 0) atomicAnd(&s[0], 0); }
    { unsigned w = ea[2 * (t * 468) + 1]; if (w != 0) atomicAnd(&s[1], 0); }
    { unsigned w = ba[2 * (t * 117) + 1]; if (w != 0) atomicAnd(&s[2], 0); }
    __syncthreads();
    if (t == 0) { g_is64_ei = s[0]; g_is64_ea = s[1]; g_is64_b = s[2]; }
}

__global__ void cvt_edges_kernel(const void* __restrict__ ei, const void* __restrict__ ea) {
    int e = blockIdx.x * blockDim.x + threadIdx.x;
    if (e >= NE) return;
    long long s, d, r;
    if (g_is64_ei) { const long long* p = (const long long*)ei; s = p[e]; d = p[NE + e]; }
    else           { const int* p = (const int*)ei;             s = p[e]; d = p[NE + e]; }
    if (g_is64_ea) r = ((const long long*)ea)[e];
    else           r = ((const int*)ea)[e];
    g_src[e] = (int)(s < 0 ? 0 : (s >= NN ? NN - 1 : s));
    g_dst[e] = (int)(d < 0 ? 0 : (d >= NN ? NN - 1 : d));
    g_rel[e] = (int)(r & 3);
}

__global__ void cvt_batch_kernel(const void* __restrict__ ba) {
    int i = blockIdx.x * blockDim.x + threadIdx.x;
    if (i >= NN) return;
    long long b = g_is64_b ? ((const long long*)ba)[i] : (long long)((const int*)ba)[i];
    g_bat[i] = (int)(b < 0 ? 0 : (b >= NG ? NG - 1 : b));
}

// ---------------- bf16 hi/lo conversions ----------------
__device__ __forceinline__ void split_bf16(float v, __nv_bfloat16& hi, __nv_bfloat16& lo) {
    hi = __float2bfloat16(v);
    lo = __float2bfloat16(v - __bfloat162float(hi));
}

__global__ void cvt_x_kernel(const float* __restrict__ x) {
    int i = blockIdx.x * blockDim.x + threadIdx.x;
    if (i >= NN * DIN) return;
    __nv_bfloat16 h, l; split_bf16(x[i], h, l);
    g_xh[i] = h; g_xl[i] = l;
}

// layer0 weights transposed: g_wt[n][k], n in [0,1280), k in [0,768)
__global__ void cvt_w0_kernel(const float* __restrict__ w0, const float* __restrict__ root0) {
    int i = blockIdx.x * blockDim.x + threadIdx.x;
    if (i >= W0_ELEMS) return;
    int n = i / DIN, k = i - n * DIN;
    float v = (n < NR * DH) ? w0[((size_t)(n >> 8) * DIN + k) * DH + (n & 255)]
                            : root0[(size_t)k * DH + (n - NR * DH)];
    __nv_bfloat16 h, l; split_bf16(v, h, l);
    g_wth[i] = h; g_wtl[i] = l;
}

// layers 1..5: g_wt[W0 + l5*WR + n*256 + k]
__global__ void cvt_wrest_kernel(const float* __restrict__ w_rest, const float* __restrict__ root_rest) {
    int i = blockIdx.x * blockDim.x + threadIdx.x;
    if (i >= 5 * WR_ELEMS) return;
    int l5 = i / WR_ELEMS;
    int rem = i - l5 * WR_ELEMS;
    int n = rem >> 8, k = rem & 255;
    float v = (n < NR * DH)
        ? w_rest[(((size_t)l5 * NR + (n >> 8)) * DH + k) * DH + (n & 255)]
        : root_rest[((size_t)l5 * DH + k) * DH + (n - NR * DH)];
    __nv_bfloat16 h, l; split_bf16(v, h, l);
    g_wth[W0_ELEMS + i] = h; g_wtl[W0_ELEMS + i] = l;
}

// ---------------- small utility kernels ----------------
__global__ void zero_cnt_kernel() {
    int i = blockIdx.x * blockDim.x + threadIdx.x;
    if (i < NR * NN) g_cnt[i] = 0.f;
}
__global__ void count_edges_kernel() {
    int e = blockIdx.x * blockDim.x + threadIdx.x;
    if (e >= NE) return;
    atomicAdd(&g_cnt[g_rel[e] * NN + g_dst[e]], 1.f);
}
__global__ void make_inv_kernel() {
    int i = blockIdx.x * blockDim.x + threadIdx.x;
    if (i < NR * NN) g_invcnt[i] = 1.f / fmaxf(g_cnt[i], 1.f);
}
__global__ void zero_pool_kernel() {
    int i = blockIdx.x * blockDim.x + threadIdx.x;
    if (i < NG * DH) { g_psum[i] = 0.f; g_pmax[i] = 0; }
    if (i < NG) g_gcnt[i] = 0.f;
}

// ---------------- mma.sync GEMM: C[60000 x 1280] = A @ [W0|W1|W2|W3|root], 3-pass bf16 ----------------
// Block tile 128x128x32, 8 warps (2m x 4n), warp tile 64x32. Smem rows padded to 40 bf16
// (80B stride -> ldmatrix conflict-free). Virtual cols [0,1024) -> g_y, [1024,1280) -> g_acc+bias.
#define SP 40

__global__ __launch_bounds__(256, 2) void gemm_mma(int layer, const float* __restrict__ bias)
{
    __shared__ __align__(16) __nv_bfloat16 sAh[128 * SP];
    __shared__ __align__(16) __nv_bfloat16 sAl[128 * SP];
    __shared__ __align__(16) __nv_bfloat16 sBh[128 * SP];
    __shared__ __align__(16) __nv_bfloat16 sBl[128 * SP];

    const int K = layer ? DH : DIN;
    const size_t boff = layer ? (size_t)W0_ELEMS + (size_t)(layer - 1) * WR_ELEMS : 0;
    const __nv_bfloat16* __restrict__ Ah = layer ? (const __nv_bfloat16*)g_hbh : (const __nv_bfloat16*)g_xh;
    const __nv_bfloat16* __restrict__ Al = layer ? (const __nv_bfloat16*)g_hbl : (const __nv_bfloat16*)g_xl;
    const __nv_bfloat16* __restrict__ Bh = (const __nv_bfloat16*)g_wth + boff;
    const __nv_bfloat16* __restrict__ Bl = (const __nv_bfloat16*)g_wtl + boff;

    const int bm = blockIdx.x * 128;
    const int cn = blockIdx.y * 128;

    const int tid = threadIdx.x, lane = tid & 31, wid = tid >> 5;
    const int m_warp = (wid >> 2) * 64, n_warp = (wid & 3) * 32;

    const uint32_t aAh = smem_to_u32(sAh), aAl = smem_to_u32(sAl);
    const uint32_t aBh = smem_to_u32(sBh), aBl = smem_to_u32(sBl);

    float acc[4][4][4] = {};

    // ldmatrix per-lane address components
    const int a_row = lane & 15;               // A: row within 16-row frag
    const int a_kb  = (lane >> 4) << 4;        // A: +16B for k8-15 half
    const int bg    = lane >> 3;               // B: matrix group 0..3
    const int b_row = ((bg & 2) << 2) + (lane & 7);
    const int b_kb  = (bg & 1) << 4;

    for (int k0 = 0; k0 < K; k0 += 32) {
        #pragma unroll
        for (int i = 0; i < 2; i++) {
            int u = i * 256 + tid;
            int r = u >> 2, c8 = u & 3;
            int so = r * SP + c8 * 8;
            size_t ga = (size_t)(bm + r) * K + k0 + c8 * 8;
            size_t gb = (size_t)(cn + r) * K + k0 + c8 * 8;
            *(uint4*)(sAh + so) = *(const uint4*)(Ah + ga);
            *(uint4*)(sAl + so) = *(const uint4*)(Al + ga);
            *(uint4*)(sBh + so) = *(const uint4*)(Bh + gb);
            *(uint4*)(sBl + so) = *(const uint4*)(Bl + gb);
        }
        __syncthreads();

        #pragma unroll
        for (int s = 0; s < 2; s++) {
            const int akoff = s * 32 + a_kb;   // bytes within 80B row
            const int bkoff = s * 32 + b_kb;
            uint32_t ah[4][4], al[4][4];
            #pragma unroll
            for (int mi = 0; mi < 4; mi++) {
                uint32_t off = (uint32_t)(m_warp + mi * 16 + a_row) * (SP * 2) + akoff;
                ldsm4(ah[mi][0], ah[mi][1], ah[mi][2], ah[mi][3], aAh + off);
                ldsm4(al[mi][0], al[mi][1], al[mi][2], al[mi][3], aAl + off);
            }
            #pragma unroll
            for (int nb = 0; nb < 2; nb++) {
                uint32_t boffs = (uint32_t)(n_warp + nb * 16 + b_row) * (SP * 2) + bkoff;
                uint32_t bh[4];
                ldsm4(bh[0], bh[1], bh[2], bh[3], aBh + boffs);
                #pragma unroll
                for (int mi = 0; mi < 4; mi++)
                    #pragma unroll
                    for (int nj = 0; nj < 2; nj++) {
                        mma16816(acc[mi][nb * 2 + nj], ah[mi], bh[2 * nj], bh[2 * nj + 1]);
                        mma16816(acc[mi][nb * 2 + nj], al[mi], bh[2 * nj], bh[2 * nj + 1]);
                    }
            }
            #pragma unroll
            for (int nb = 0; nb < 2; nb++) {
                uint32_t boffs = (uint32_t)(n_warp + nb * 16 + b_row) * (SP * 2) + bkoff;
                uint32_t bl[4];
                ldsm4(bl[0], bl[1], bl[2], bl[3], aBl + boffs);
                #pragma unroll
                for (int mi = 0; mi < 4; mi++)
                    #pragma unroll
                    for (int nj = 0; nj < 2; nj++)
                        mma16816(acc[mi][nb * 2 + nj], ah[mi], bl[2 * nj], bl[2 * nj + 1]);
            }
        }
        __syncthreads();
    }

    // epilogue: c0,c1 -> (row, col), c2,c3 -> (row+8, col)
    const bool isRoot = (cn >= NR * DH);
    const int rel = cn >> 8;
    const int cb128 = cn & 255;          // col base within DH for y path
    #pragma unroll
    for (int mi = 0; mi < 4; mi++) {
        int r0 = bm + m_warp + mi * 16 + (lane >> 2);
        #pragma unroll
        for (int half = 0; half < 2; half++) {
            int r = r0 + half * 8;
            if (r >= NN) continue;
            #pragma unroll
            for (int nj = 0; nj < 4; nj++) {
                int c = n_warp + nj * 8 + (lane & 3) * 2;
                float v0 = acc[mi][nj][half * 2 + 0];
                float v1 = acc[mi][nj][half * 2 + 1];
                if (isRoot) {
                    int col = (cn - NR * DH) + c;
                    float2 o = make_float2(v0 + bias[col], v1 + bias[col + 1]);
                    *(float2*)(g_acc + (size_t)r * DH + col) = o;
                } else {
                    *(float2*)(g_y + ((size_t)rel * NN + r) * DH + cb128 + c) = make_float2(v0, v1);
                }
            }
        }
    }
}

// ---------------- edge scatter: acc[dst] += y[rel][src] * invcnt[rel][dst] ----------------
__global__ __launch_bounds__(256) void edge_scatter() {
    int e = blockIdx.x * 8 + (threadIdx.x >> 5);
    if (e >= NE) return;
    int lane = threadIdx.x & 31;
    int src = g_src[e];
    int dst = g_dst[e];
    int rel = g_rel[e];
    float inv = g_invcnt[rel * NN + dst];
    const float4* ys = (const float4*)(g_y + ((size_t)rel * NN + src) * DH);
    float* ad = g_acc + (size_t)dst * DH;
    #pragma unroll
    for (int i = 0; i < 2; i++) {
        float4 v = ys[lane + 32 * i];
        int base = (lane + 32 * i) * 4;
        atomicAdd(&ad[base + 0], v.x * inv);
        atomicAdd(&ad[base + 1], v.y * inv);
        atomicAdd(&ad[base + 2], v.z * inv);
        atomicAdd(&ad[base + 3], v.w * inv);
    }
}

// ---------------- relu + bf16 split for next layer ----------------
__global__ void relu_bf_kernel(int writeF32) {
    int i = blockIdx.x * blockDim.x + threadIdx.x;
    if (i >= NN * DH) return;
    float v = fmaxf(g_acc[i], 0.f);
    __nv_bfloat16 h, l; split_bf16(v, h, l);
    g_hbh[i] = h; g_hbl[i] = l;
    if (writeF32) g_h[i] = v;
}

// ---------------- graph pooling (sum + max + count) ----------------
__global__ void pool_kernel() {
    int idx = blockIdx.x * blockDim.x + threadIdx.x;
    if (idx >= NN * DH) return;
    int node = idx >> 8;
    int d    = idx & (DH - 1);
    int g    = g_bat[node];
    float v  = g_h[idx];
    atomicAdd(&g_psum[g * DH + d], v);
    atomicMax(&g_pmax[g * DH + d], __float_as_int(v));
    if (d == 0) atomicAdd(&g_gcnt[g], 1.f);
}

// ---------------- final MLP head ----------------
__global__ __launch_bounds__(128) void mlp_kernel(
    const float* __restrict__ fc1w, const float* __restrict__ fc1b,
    const float* __restrict__ fc2w, const float* __restrict__ fc2b,
    float* __restrict__ out)
{
    __shared__ float gv[2 * DH];
    __shared__ float partial[4];
    int gi = blockIdx.x;
    int t  = threadIdx.x;
    float cnt = fmaxf(g_gcnt[gi], 1.f);
    for (int i = t; i < DH; i += 128) {
        gv[i]      = g_psum[gi * DH + i] / cnt;
        gv[DH + i] = __int_as_float(g_pmax[gi * DH + i]);
    }
    __syncthreads();
    float a = fc1b[t];
    #pragma unroll 8
    for (int i = 0; i < 2 * DH; i++) a += gv[i] * fc1w[i * 128 + t];
    a = fmaxf(a, 0.f);
    float p = a * fc2w[t];
    #pragma unroll
    for (int o = 16; o > 0; o >>= 1) p += __shfl_down_sync(0xffffffffu, p, o);
    if ((t & 31) == 0) partial[t >> 5] = p;
    __syncthreads();
    if (t == 0) {
        float s = partial[0] + partial[1] + partial[2] + partial[3] + fc2b[0];
        out[gi] = 1.f / (1.f + expf(-s));
    }
}

// ---------------- launch ----------------
extern "C" void kernel_launch(void* const* d_in, const int* in_sizes, int n_in,
                              void* d_out, int out_size)
{
    const float* x         = (const float*)d_in[0];
    const void*  ei        = d_in[1];
    const void*  ea        = d_in[2];
    const void*  ba        = d_in[3];
    const float* w0        = (const float*)d_in[4];
    const float* root0     = (const float*)d_in[5];
    const float* b0        = (const float*)d_in[6];
    const float* w_rest    = (const float*)d_in[7];
    const float* root_rest = (const float*)d_in[8];
    const float* b_rest    = (const float*)d_in[9];
    const float* fc1w      = (const float*)d_in[10];
    const float* fc1b      = (const float*)d_in[11];
    const float* fc2w      = (const float*)d_in[12];
    const float* fc2b      = (const float*)d_in[13];
    float* out = (float*)d_out;

    const int T = 256;

    // index decode
    detect_kernel<<<1, 256>>>((const unsigned*)ei, (const unsigned*)ea, (const unsigned*)ba);
    cvt_edges_kernel<<<(NE + T - 1) / T, T>>>(ei, ea);
    cvt_batch_kernel<<<(NN + T - 1) / T, T>>>(ba);

    // bf16 hi/lo conversions
    cvt_x_kernel<<<(NN * DIN + T - 1) / T, T>>>(x);
    cvt_w0_kernel<<<(W0_ELEMS + T - 1) / T, T>>>(w0, root0);
    cvt_wrest_kernel<<<(5 * WR_ELEMS + T - 1) / T, T>>>(w_rest, root_rest);

    // per-(relation,dst) mean normalizers
    zero_cnt_kernel<<<(NR * NN + T - 1) / T, T>>>();
    count_edges_kernel<<<(NE + T - 1) / T, T>>>();
    make_inv_kernel<<<(NR * NN + T - 1) / T, T>>>();

    dim3 ggrid((NN + 127) / 128, 10);
    const int egrid = (NE + 7) / 8;
    const int rgrid = (NN * DH + T - 1) / T;

    for (int l = 0; l < NL; l++) {
        const float* B = l ? (b_rest + (size_t)(l - 1) * DH) : b0;
        gemm_mma<<<ggrid, 256>>>(l, B);
        edge_scatter<<<egrid, 256>>>();
        relu_bf_kernel<<<rgrid, T>>>(l == NL - 1 ? 1 : 0);
    }

    zero_pool_kernel<<<(NG * DH + T - 1) / T, T>>>();
    pool_kernel<<<rgrid, T>>>();
    mlp_kernel<<<NG, 128>>>(fc1w, fc1b, fc2w, fc2b, out);
}

// round 9
// speedup vs baseline: 2.3005x; 1.1792x over previous
#include <cuda_runtime.h>
#include <cuda_bf16.h>
#include <math.h>
#include <stdint.h>

#define NN 60000
#define NNP 60128          // padded rows (tile overrun safe)
#define NE 240000
#define NR 4
#define NG 128
#define DIN 768
#define DH 256
#define NL 6

// ---------------- scratch (static device globals; no allocation) ----------------
__device__ __align__(16) float g_h[(size_t)NN * DH];          // fp32 activations (for pooling)
__device__ __align__(16) float g_acc[(size_t)NN * DH];        // root transform + edge accumulation
__device__ __align__(16) float g_y[(size_t)NR * NN * DH];     // per-relation transformed features
__device__ __align__(16) float g_cnt[NR * NN];
__device__ __align__(16) float g_invcnt[NR * NN];
__device__ __align__(16) float g_psum[NG * DH];
__device__ __align__(16) int   g_pmax[NG * DH];
__device__ __align__(16) float g_gcnt[NG];

// bf16 hi/lo split inputs for tensor-core GEMMs
__device__ __align__(16) __nv_bfloat16 g_xh[(size_t)NNP * DIN];
__device__ __align__(16) __nv_bfloat16 g_xl[(size_t)NNP * DIN];
__device__ __align__(16) __nv_bfloat16 g_hbh[(size_t)NNP * DH];
__device__ __align__(16) __nv_bfloat16 g_hbl[(size_t)NNP * DH];
// transposed weights: layer0 [1280][768] then layers1-5 [1280][256] each
#define W0_ELEMS (1280 * 768)
#define WR_ELEMS (1280 * 256)
#define WT_TOTAL (W0_ELEMS + 5 * WR_ELEMS)
__device__ __align__(16) __nv_bfloat16 g_wth[WT_TOTAL];
__device__ __align__(16) __nv_bfloat16 g_wtl[WT_TOTAL];

// decoded int32 index arrays + dtype flags
__device__ int g_src[NE];
__device__ int g_dst[NE];
__device__ int g_rel[NE];
__device__ int g_bat[NN];
__device__ int g_is64_ei, g_is64_ea, g_is64_b;

// ---------------- helpers ----------------
__device__ __forceinline__ uint32_t smem_to_u32(const void* p) {
    uint32_t a;
    asm("{ .reg .u64 t; cvta.to.shared.u64 t, %1; cvt.u32.u64 %0, t; }" : "=r"(a) : "l"(p));
    return a;
}

__device__ __forceinline__ void ldsm4(uint32_t& r0, uint32_t& r1, uint32_t& r2, uint32_t& r3, uint32_t addr) {
    asm volatile("ldmatrix.sync.aligned.m8n8.x4.shared.b16 {%0,%1,%2,%3}, [%4];"
                 : "=r"(r0), "=r"(r1), "=r"(r2), "=r"(r3) : "r"(addr));
}

__device__ __forceinline__ void mma16816(float* d, const uint32_t* a, uint32_t b0, uint32_t b1) {
    asm volatile("mma.sync.aligned.m16n8k16.row.col.f32.bf16.bf16.f32 "
                 "{%0,%1,%2,%3}, {%4,%5,%6,%7}, {%8,%9}, {%0,%1,%2,%3};"
                 : "+f"(d[0]), "+f"(d[1]), "+f"(d[2]), "+f"(d[3])
                 : "r"(a[0]), "r"(a[1]), "r"(a[2]), "r"(a[3]), "r"(b0), "r"(b1));
}

__device__ __forceinline__ void cpasync16(uint32_t saddr, const void* gaddr) {
    asm volatile("cp.async.cg.shared.global [%0], [%1], 16;" :: "r"(saddr), "l"(gaddr));
}
#define CP_COMMIT() asm volatile("cp.async.commit_group;" ::: "memory")
#define CP_WAIT0()  asm volatile("cp.async.wait_group 0;" ::: "memory")
#define CP_WAIT1()  asm volatile("cp.async.wait_group 1;" ::: "memory")

__device__ __forceinline__ void red4(float* p, float a, float b, float c, float d) {
    asm volatile("red.global.add.v4.f32 [%0], {%1,%2,%3,%4};"
                 :: "l"(p), "f"(a), "f"(b), "f"(c), "f"(d) : "memory");
}

// ---------------- dtype detection ----------------
__global__ void detect_kernel(const unsigned* __restrict__ ei,
                              const unsigned* __restrict__ ea,
                              const unsigned* __restrict__ ba) {
    __shared__ int s[3];
    int t = threadIdx.x;
    if (t < 3) s[t] = 1;
    __syncthreads();
    { unsigned w = ei[2 * (t * 937) + 1]; if (w != 0) atomicAnd(&s[0], 0); }
    { unsigned w = ea[2 * (t * 468) + 1]; if (w != 0) atomicAnd(&s[1], 0); }
    { unsigned w = ba[2 * (t * 117) + 1]; if (w != 0) atomicAnd(&s[2], 0); }
    __syncthreads();
    if (t == 0) { g_is64_ei = s[0]; g_is64_ea = s[1]; g_is64_b = s[2]; }
}

__global__ void cvt_edges_kernel(const void* __restrict__ ei, const void* __restrict__ ea) {
    int e = blockIdx.x * blockDim.x + threadIdx.x;
    if (e >= NE) return;
    long long s, d, r;
    if (g_is64_ei) { const long long* p = (const long long*)ei; s = p[e]; d = p[NE + e]; }
    else           { const int* p = (const int*)ei;             s = p[e]; d = p[NE + e]; }
    if (g_is64_ea) r = ((const long long*)ea)[e];
    else           r = ((const int*)ea)[e];
    g_src[e] = (int)(s < 0 ? 0 : (s >= NN ? NN - 1 : s));
    g_dst[e] = (int)(d < 0 ? 0 : (d >= NN ? NN - 1 : d));
    g_rel[e] = (int)(r & 3);
}

__global__ void cvt_batch_kernel(const void* __restrict__ ba) {
    int i = blockIdx.x * blockDim.x + threadIdx.x;
    if (i >= NN) return;
    long long b = g_is64_b ? ((const long long*)ba)[i] : (long long)((const int*)ba)[i];
    g_bat[i] = (int)(b < 0 ? 0 : (b >= NG ? NG - 1 : b));
}

// ---------------- bf16 hi/lo conversions ----------------
__device__ __forceinline__ void split_bf16(float v, __nv_bfloat16& hi, __nv_bfloat16& lo) {
    hi = __float2bfloat16(v);
    lo = __float2bfloat16(v - __bfloat162float(hi));
}

__global__ void cvt_x_kernel(const float* __restrict__ x) {
    int i = blockIdx.x * blockDim.x + threadIdx.x;
    if (i >= NN * DIN) return;
    __nv_bfloat16 h, l; split_bf16(x[i], h, l);
    g_xh[i] = h; g_xl[i] = l;
}

// layer0 weights transposed: g_wt[n][k], n in [0,1280), k in [0,768)
__global__ void cvt_w0_kernel(const float* __restrict__ w0, const float* __restrict__ root0) {
    int i = blockIdx.x * blockDim.x + threadIdx.x;
    if (i >= W0_ELEMS) return;
    int n = i / DIN, k = i - n * DIN;
    float v = (n < NR * DH) ? w0[((size_t)(n >> 8) * DIN + k) * DH + (n & 255)]
                            : root0[(size_t)k * DH + (n - NR * DH)];
    __nv_bfloat16 h, l; split_bf16(v, h, l);
    g_wth[i] = h; g_wtl[i] = l;
}

// layers 1..5: g_wt[W0 + l5*WR + n*256 + k]
__global__ void cvt_wrest_kernel(const float* __restrict__ w_rest, const float* __restrict__ root_rest) {
    int i = blockIdx.x * blockDim.x + threadIdx.x;
    if (i >= 5 * WR_ELEMS) return;
    int l5 = i / WR_ELEMS;
    int rem = i - l5 * WR_ELEMS;
    int n = rem >> 8, k = rem & 255;
    float v = (n < NR * DH)
        ? w_rest[(((size_t)l5 * NR + (n >> 8)) * DH + k) * DH + (n & 255)]
        : root_rest[((size_t)l5 * DH + k) * DH + (n - NR * DH)];
    __nv_bfloat16 h, l; split_bf16(v, h, l);
    g_wth[W0_ELEMS + i] = h; g_wtl[W0_ELEMS + i] = l;
}

// ---------------- small utility kernels ----------------
__global__ void zero_cnt_kernel() {
    int i = blockIdx.x * blockDim.x + threadIdx.x;
    if (i < NR * NN) g_cnt[i] = 0.f;
}
__global__ void count_edges_kernel() {
    int e = blockIdx.x * blockDim.x + threadIdx.x;
    if (e >= NE) return;
    atomicAdd(&g_cnt[g_rel[e] * NN + g_dst[e]], 1.f);
}
__global__ void make_inv_kernel() {
    int i = blockIdx.x * blockDim.x + threadIdx.x;
    if (i < NR * NN) g_invcnt[i] = 1.f / fmaxf(g_cnt[i], 1.f);
}
__global__ void zero_pool_kernel() {
    int i = blockIdx.x * blockDim.x + threadIdx.x;
    if (i < NG * DH) { g_psum[i] = 0.f; g_pmax[i] = 0; }
    if (i < NG) g_gcnt[i] = 0.f;
}

// ---------------- mma.sync GEMM, cp.async double-buffered ----------------
// C[60000 x 1280] = A[60000 x K] @ [W0|W1|W2|W3|root]^T, 3-pass bf16 hi/lo.
// Block tile 128x128x32, 8 warps (2m x 4n), warp tile 64x32. Smem rows padded to
// SP=40 bf16 (80B stride -> ldmatrix conflict-free; 16B-aligned for cp.async).
// Dynamic smem: 2 stages x 4 buffers x 10240B = 81920B.
#define SP 40
#define STG_BYTES (4 * 128 * SP * 2)      // 40960 per stage
#define BUF_BYTES (128 * SP * 2)          // 10240 per buffer
#define GSMEM_TOTAL (2 * STG_BYTES)

__global__ __launch_bounds__(256, 2) void gemm_mma(int layer, const float* __restrict__ bias)
{
    extern __shared__ char dsm[];
    const uint32_t sb = smem_to_u32(dsm);

    const int K = layer ? DH : DIN;
    const size_t boff = layer ? (size_t)W0_ELEMS + (size_t)(layer - 1) * WR_ELEMS : 0;
    const __nv_bfloat16* __restrict__ Ah = layer ? (const __nv_bfloat16*)g_hbh : (const __nv_bfloat16*)g_xh;
    const __nv_bfloat16* __restrict__ Al = layer ? (const __nv_bfloat16*)g_hbl : (const __nv_bfloat16*)g_xl;
    const __nv_bfloat16* __restrict__ Bh = (const __nv_bfloat16*)g_wth + boff;
    const __nv_bfloat16* __restrict__ Bl = (const __nv_bfloat16*)g_wtl + boff;

    const int bm = blockIdx.x * 128;
    const int cn = blockIdx.y * 128;

    const int tid = threadIdx.x, lane = tid & 31, wid = tid >> 5;
    const int m_warp = (wid >> 2) * 64, n_warp = (wid & 3) * 32;

    float acc[4][4][4] = {};

    // per-thread load coords (8 x cp.async of 16B per stage: 2 iters x 4 buffers)
    const int l_r0 = tid >> 2;            // 0..63
    const int l_c8 = tid & 3;             // 16B chunk within 64B row-chunk
    const uint32_t so0 = (uint32_t)(l_r0 * SP + l_c8 * 8) * 2;
    const uint32_t so1 = (uint32_t)((l_r0 + 64) * SP + l_c8 * 8) * 2;

    // ldmatrix per-lane address components
    const int a_row = lane & 15;
    const int a_kb  = (lane >> 4) << 4;
    const int bg    = lane >> 3;
    const int b_row = ((bg & 2) << 2) + (lane & 7);
    const int b_kb  = (bg & 1) << 4;

    const int nch = K >> 5;

    // stage loader
    auto load_stage = [&](int st, int k0) {
        const uint32_t s0 = sb + st * STG_BYTES;
        size_t ga0 = (size_t)(bm + l_r0) * K + k0 + l_c8 * 8;
        size_t gb0 = (size_t)(cn + l_r0) * K + k0 + l_c8 * 8;
        size_t ga1 = ga0 + (size_t)64 * K;
        size_t gb1 = gb0 + (size_t)64 * K;
        cpasync16(s0 + 0 * BUF_BYTES + so0, Ah + ga0);
        cpasync16(s0 + 1 * BUF_BYTES + so0, Al + ga0);
        cpasync16(s0 + 2 * BUF_BYTES + so0, Bh + gb0);
        cpasync16(s0 + 3 * BUF_BYTES + so0, Bl + gb0);
        cpasync16(s0 + 0 * BUF_BYTES + so1, Ah + ga1);
        cpasync16(s0 + 1 * BUF_BYTES + so1, Al + ga1);
        cpasync16(s0 + 2 * BUF_BYTES + so1, Bh + gb1);
        cpasync16(s0 + 3 * BUF_BYTES + so1, Bl + gb1);
    };

    load_stage(0, 0);
    CP_COMMIT();

    for (int c = 0; c < nch; c++) {
        const bool more = (c + 1 < nch);
        if (more) { load_stage((c + 1) & 1, (c + 1) << 5); CP_COMMIT(); }
        if (more) CP_WAIT1(); else CP_WAIT0();
        __syncthreads();

        const uint32_t s0  = sb + (c & 1) * STG_BYTES;
        const uint32_t aAh = s0;
        const uint32_t aAl = s0 + 1 * BUF_BYTES;
        const uint32_t aBh = s0 + 2 * BUF_BYTES;
        const uint32_t aBl = s0 + 3 * BUF_BYTES;

        #pragma unroll
        for (int s = 0; s < 2; s++) {
            const int akoff = s * 32 + a_kb;   // bytes within 80B row
            const int bkoff = s * 32 + b_kb;
            uint32_t ah[4][4], al[4][4];
            #pragma unroll
            for (int mi = 0; mi < 4; mi++) {
                uint32_t off = (uint32_t)(m_warp + mi * 16 + a_row) * (SP * 2) + akoff;
                ldsm4(ah[mi][0], ah[mi][1], ah[mi][2], ah[mi][3], aAh + off);
                ldsm4(al[mi][0], al[mi][1], al[mi][2], al[mi][3], aAl + off);
            }
            #pragma unroll
            for (int nb = 0; nb < 2; nb++) {
                uint32_t boffs = (uint32_t)(n_warp + nb * 16 + b_row) * (SP * 2) + bkoff;
                uint32_t bh[4];
                ldsm4(bh[0], bh[1], bh[2], bh[3], aBh + boffs);
                #pragma unroll
                for (int mi = 0; mi < 4; mi++)
                    #pragma unroll
                    for (int nj = 0; nj < 2; nj++) {
                        mma16816(acc[mi][nb * 2 + nj], ah[mi], bh[2 * nj], bh[2 * nj + 1]);
                        mma16816(acc[mi][nb * 2 + nj], al[mi], bh[2 * nj], bh[2 * nj + 1]);
                    }
            }
            #pragma unroll
            for (int nb = 0; nb < 2; nb++) {
                uint32_t boffs = (uint32_t)(n_warp + nb * 16 + b_row) * (SP * 2) + bkoff;
                uint32_t bl[4];
                ldsm4(bl[0], bl[1], bl[2], bl[3], aBl + boffs);
                #pragma unroll
                for (int mi = 0; mi < 4; mi++)
                    #pragma unroll
                    for (int nj = 0; nj < 2; nj++)
                        mma16816(acc[mi][nb * 2 + nj], ah[mi], bl[2 * nj], bl[2 * nj + 1]);
            }
        }
        __syncthreads();
    }

    // epilogue: c0,c1 -> (row, col), c2,c3 -> (row+8, col)
    const bool isRoot = (cn >= NR * DH);
    const int rel = cn >> 8;
    const int cb128 = cn & 255;
    #pragma unroll
    for (int mi = 0; mi < 4; mi++) {
        int r0 = bm + m_warp + mi * 16 + (lane >> 2);
        #pragma unroll
        for (int half = 0; half < 2; half++) {
            int r = r0 + half * 8;
            if (r >= NN) continue;
            #pragma unroll
            for (int nj = 0; nj < 4; nj++) {
                int c = n_warp + nj * 8 + (lane & 3) * 2;
                float v0 = acc[mi][nj][half * 2 + 0];
                float v1 = acc[mi][nj][half * 2 + 1];
                if (isRoot) {
                    int col = (cn - NR * DH) + c;
                    float2 o = make_float2(v0 + bias[col], v1 + bias[col + 1]);
                    *(float2*)(g_acc + (size_t)r * DH + col) = o;
                } else {
                    *(float2*)(g_y + ((size_t)rel * NN + r) * DH + cb128 + c) = make_float2(v0, v1);
                }
            }
        }
    }
}

// ---------------- edge scatter: acc[dst] += y[rel][src] * invcnt[rel][dst] ----------------
__global__ __launch_bounds__(256) void edge_scatter() {
    int e = blockIdx.x * 8 + (threadIdx.x >> 5);
    if (e >= NE) return;
    int lane = threadIdx.x & 31;
    int src = g_src[e];
    int dst = g_dst[e];
    int rel = g_rel[e];
    float inv = g_invcnt[rel * NN + dst];
    const float4* ys = (const float4*)(g_y + ((size_t)rel * NN + src) * DH);
    float* ad = g_acc + (size_t)dst * DH;
    #pragma unroll
    for (int i = 0; i < 2; i++) {
        float4 v = ys[lane + 32 * i];
        red4(ad + (lane + 32 * i) * 4, v.x * inv, v.y * inv, v.z * inv, v.w * inv);
    }
}

// ---------------- relu + bf16 split for next layer ----------------
__global__ void relu_bf_kernel(int writeF32) {
    int i = blockIdx.x * blockDim.x + threadIdx.x;
    if (i >= NN * DH) return;
    float v = fmaxf(g_acc[i], 0.f);
    __nv_bfloat16 h, l; split_bf16(v, h, l);
    g_hbh[i] = h; g_hbl[i] = l;
    if (writeF32) g_h[i] = v;
}

// ---------------- graph pooling (sum + max + count) ----------------
__global__ void pool_kernel() {
    int idx = blockIdx.x * blockDim.x + threadIdx.x;
    if (idx >= NN * DH) return;
    int node = idx >> 8;
    int d    = idx & (DH - 1);
    int g    = g_bat[node];
    float v  = g_h[idx];
    atomicAdd(&g_psum[g * DH + d], v);
    atomicMax(&g_pmax[g * DH + d], __float_as_int(v));
    if (d == 0) atomicAdd(&g_gcnt[g], 1.f);
}

// ---------------- final MLP head ----------------
__global__ __launch_bounds__(128) void mlp_kernel(
    const float* __restrict__ fc1w, const float* __restrict__ fc1b,
    const float* __restrict__ fc2w, const float* __restrict__ fc2b,
    float* __restrict__ out)
{
    __shared__ float gv[2 * DH];
    __shared__ float partial[4];
    int gi = blockIdx.x;
    int t  = threadIdx.x;
    float cnt = fmaxf(g_gcnt[gi], 1.f);
    for (int i = t; i < DH; i += 128) {
        gv[i]      = g_psum[gi * DH + i] / cnt;
        gv[DH + i] = __int_as_float(g_pmax[gi * DH + i]);
    }
    __syncthreads();
    float a = fc1b[t];
    #pragma unroll 8
    for (int i = 0; i < 2 * DH; i++) a += gv[i] * fc1w[i * 128 + t];
    a = fmaxf(a, 0.f);
    float p = a * fc2w[t];
    #pragma unroll
    for (int o = 16; o > 0; o >>= 1) p += __shfl_down_sync(0xffffffffu, p, o);
    if ((t & 31) == 0) partial[t >> 5] = p;
    __syncthreads();
    if (t == 0) {
        float s = partial[0] + partial[1] + partial[2] + partial[3] + fc2b[0];
        out[gi] = 1.f / (1.f + expf(-s));
    }
}

// ---------------- launch ----------------
extern "C" void kernel_launch(void* const* d_in, const int* in_sizes, int n_in,
                              void* d_out, int out_size)
{
    const float* x         = (const float*)d_in[0];
    const void*  ei        = d_in[1];
    const void*  ea        = d_in[2];
    const void*  ba        = d_in[3];
    const float* w0        = (const float*)d_in[4];
    const float* root0     = (const float*)d_in[5];
    const float* b0        = (const float*)d_in[6];
    const float* w_rest    = (const float*)d_in[7];
    const float* root_rest = (const float*)d_in[8];
    const float* b_rest    = (const float*)d_in[9];
    const float* fc1w      = (const float*)d_in[10];
    const float* fc1b      = (const float*)d_in[11];
    const float* fc2w      = (const float*)d_in[12];
    const float* fc2b      = (const float*)d_in[13];
    float* out = (float*)d_out;

    const int T = 256;

    cudaFuncSetAttribute(gemm_mma, cudaFuncAttributeMaxDynamicSharedMemorySize, GSMEM_TOTAL);

    // index decode
    detect_kernel<<<1, 256>>>((const unsigned*)ei, (const unsigned*)ea, (const unsigned*)ba);
    cvt_edges_kernel<<<(NE + T - 1) / T, T>>>(ei, ea);
    cvt_batch_kernel<<<(NN + T - 1) / T, T>>>(ba);

    // bf16 hi/lo conversions
    cvt_x_kernel<<<(NN * DIN + T - 1) / T, T>>>(x);
    cvt_w0_kernel<<<(W0_ELEMS + T - 1) / T, T>>>(w0, root0);
    cvt_wrest_kernel<<<(5 * WR_ELEMS + T - 1) / T, T>>>(w_rest, root_rest);

    // per-(relation,dst) mean normalizers
    zero_cnt_kernel<<<(NR * NN + T - 1) / T, T>>>();
    count_edges_kernel<<<(NE + T - 1) / T, T>>>();
    make_inv_kernel<<<(NR * NN + T - 1) / T, T>>>();

    dim3 ggrid((NN + 127) / 128, 10);
    const int egrid = (NE + 7) / 8;
    const int rgrid = (NN * DH + T - 1) / T;

    for (int l = 0; l < NL; l++) {
        const float* B = l ? (b_rest + (size_t)(l - 1) * DH) : b0;
        gemm_mma<<<ggrid, 256, GSMEM_TOTAL>>>(l, B);
        edge_scatter<<<egrid, 256>>>();
        relu_bf_kernel<<<rgrid, T>>>(l == NL - 1 ? 1 : 0);
    }

    zero_pool_kernel<<<(NG * DH + T - 1) / T, T>>>();
    pool_kernel<<<rgrid, T>>>();
    mlp_kernel<<<NG, 128>>>(fc1w, fc1b, fc2w, fc2b, out);
}

// round 13
// speedup vs baseline: 2.5200x; 1.0954x over previous
#include <cuda_runtime.h>
#include <cuda_bf16.h>
#include <math.h>
#include <stdint.h>

#define NN 60000
#define NNP 60128          // padded rows (tile overrun safe)
#define NE 240000
#define NR 4
#define NG 128
#define DIN 768
#define DH 256
#define NL 6

// ---------------- scratch (static device globals; no allocation) ----------------
__device__ __align__(16) float g_h[(size_t)NN * DH];          // fp32 activations (for pooling)
__device__ __align__(16) float g_acc[(size_t)NN * DH];        // root transform + edge accumulation
__device__ __align__(16) float g_y[(size_t)NR * NN * DH];     // per-relation transformed features
__device__ __align__(16) float g_cnt[NR * NN];
__device__ __align__(16) float g_invcnt[NR * NN];
__device__ __align__(16) float g_psum[NG * DH];
__device__ __align__(16) int   g_pmax[NG * DH];
__device__ __align__(16) float g_gcnt[NG];

// bf16 hi/lo split inputs for tensor-core GEMMs
__device__ __align__(16) __nv_bfloat16 g_xh[(size_t)NNP * DIN];
__device__ __align__(16) __nv_bfloat16 g_xl[(size_t)NNP * DIN];
__device__ __align__(16) __nv_bfloat16 g_hbh[(size_t)NNP * DH];
__device__ __align__(16) __nv_bfloat16 g_hbl[(size_t)NNP * DH];
// transposed weights: layer0 [1280][768] then layers1-5 [1280][256] each
#define W0_ELEMS (1280 * 768)
#define WR_ELEMS (1280 * 256)
#define WT_TOTAL (W0_ELEMS + 5 * WR_ELEMS)
__device__ __align__(16) __nv_bfloat16 g_wth[WT_TOTAL];
__device__ __align__(16) __nv_bfloat16 g_wtl[WT_TOTAL];

// decoded int32 index arrays + dtype flags
__device__ int g_src[NE];
__device__ int g_dst[NE];
__device__ int g_rel[NE];
__device__ int g_bat[NN];
__device__ int g_is64_ei, g_is64_ea, g_is64_b;

// ---------------- helpers ----------------
__device__ __forceinline__ uint32_t smem_to_u32(const void* p) {
    uint32_t a;
    asm("{ .reg .u64 t; cvta.to.shared.u64 t, %1; cvt.u32.u64 %0, t; }" : "=r"(a) : "l"(p));
    return a;
}

__device__ __forceinline__ void ldsm4(uint32_t& r0, uint32_t& r1, uint32_t& r2, uint32_t& r3, uint32_t addr) {
    asm volatile("ldmatrix.sync.aligned.m8n8.x4.shared.b16 {%0,%1,%2,%3}, [%4];"
                 : "=r"(r0), "=r"(r1), "=r"(r2), "=r"(r3) : "r"(addr));
}

__device__ __forceinline__ void mma16816(float* d, const uint32_t* a, uint32_t b0, uint32_t b1) {
    asm volatile("mma.sync.aligned.m16n8k16.row.col.f32.bf16.bf16.f32 "
                 "{%0,%1,%2,%3}, {%4,%5,%6,%7}, {%8,%9}, {%0,%1,%2,%3};"
                 : "+f"(d[0]), "+f"(d[1]), "+f"(d[2]), "+f"(d[3])
                 : "r"(a[0]), "r"(a[1]), "r"(a[2]), "r"(a[3]), "r"(b0), "r"(b1));
}

__device__ __forceinline__ void cpasync16(uint32_t saddr, const void* gaddr) {
    asm volatile("cp.async.cg.shared.global [%0], [%1], 16;" :: "r"(saddr), "l"(gaddr));
}
#define CP_COMMIT() asm volatile("cp.async.commit_group;" ::: "memory")
#define CP_WAIT0()  asm volatile("cp.async.wait_group 0;" ::: "memory")
#define CP_WAIT1()  asm volatile("cp.async.wait_group 1;" ::: "memory")

__device__ __forceinline__ void red4(float* p, float a, float b, float c, float d) {
    asm volatile("red.global.add.v4.f32 [%0], {%1,%2,%3,%4};"
                 :: "l"(p), "f"(a), "f"(b), "f"(c), "f"(d) : "memory");
}

__device__ __forceinline__ void split_bf16(float v, __nv_bfloat16& hi, __nv_bfloat16& lo) {
    hi = __float2bfloat16(v);
    lo = __float2bfloat16(v - __bfloat162float(hi));
}

// ---------------- dtype detection ----------------
__global__ void detect_kernel(const unsigned* __restrict__ ei,
                              const unsigned* __restrict__ ea,
                              const unsigned* __restrict__ ba) {
    __shared__ int s[3];
    int t = threadIdx.x;
    if (t < 3) s[t] = 1;
    __syncthreads();
    { unsigned w = ei[2 * (t * 937) + 1]; if (w != 0) atomicAnd(&s[0], 0); }
    { unsigned w = ea[2 * (t * 468) + 1]; if (w != 0) atomicAnd(&s[1], 0); }
    { unsigned w = ba[2 * (t * 117) + 1]; if (w != 0) atomicAnd(&s[2], 0); }
    __syncthreads();
    if (t == 0) { g_is64_ei = s[0]; g_is64_ea = s[1]; g_is64_b = s[2]; }
}

__global__ void cvt_edges_kernel(const void* __restrict__ ei, const void* __restrict__ ea) {
    int e = blockIdx.x * blockDim.x + threadIdx.x;
    if (e >= NE) return;
    long long s, d, r;
    if (g_is64_ei) { const long long* p = (const long long*)ei; s = p[e]; d = p[NE + e]; }
    else           { const int* p = (const int*)ei;             s = p[e]; d = p[NE + e]; }
    if (g_is64_ea) r = ((const long long*)ea)[e];
    else           r = ((const int*)ea)[e];
    g_src[e] = (int)(s < 0 ? 0 : (s >= NN ? NN - 1 : s));
    g_dst[e] = (int)(d < 0 ? 0 : (d >= NN ? NN - 1 : d));
    g_rel[e] = (int)(r & 3);
}

__global__ void cvt_batch_kernel(const void* __restrict__ ba) {
    int i = blockIdx.x * blockDim.x + threadIdx.x;
    if (i >= NN) return;
    long long b = g_is64_b ? ((const long long*)ba)[i] : (long long)((const int*)ba)[i];
    g_bat[i] = (int)(b < 0 ? 0 : (b >= NG ? NG - 1 : b));
}

// ---------------- bf16 hi/lo conversions (vectorized: 8 elems/thread) ----------------
__global__ void cvt_x_kernel(const float* __restrict__ x) {
    int i = blockIdx.x * blockDim.x + threadIdx.x;
    if (i >= NN * DIN / 8) return;
    const float4* p = (const float4*)x + (size_t)i * 2;
    float4 v0 = p[0], v1 = p[1];
    float vv[8] = {v0.x, v0.y, v0.z, v0.w, v1.x, v1.y, v1.z, v1.w};
    union { __nv_bfloat16 b[8]; uint4 u; } H, L;
    #pragma unroll
    for (int j = 0; j < 8; j++) split_bf16(vv[j], H.b[j], L.b[j]);
    ((uint4*)g_xh)[i] = H.u;
    ((uint4*)g_xl)[i] = L.u;
}

// layer0 weights transposed: g_wt[n][k], n in [0,1280), k in [0,768)
__global__ void cvt_w0_kernel(const float* __restrict__ w0, const float* __restrict__ root0) {
    int i = blockIdx.x * blockDim.x + threadIdx.x;
    if (i >= W0_ELEMS) return;
    int n = i / DIN, k = i - n * DIN;
    float v = (n < NR * DH) ? w0[((size_t)(n >> 8) * DIN + k) * DH + (n & 255)]
                            : root0[(size_t)k * DH + (n - NR * DH)];
    __nv_bfloat16 h, l; split_bf16(v, h, l);
    g_wth[i] = h; g_wtl[i] = l;
}

// layers 1..5: g_wt[W0 + l5*WR + n*256 + k]
__global__ void cvt_wrest_kernel(const float* __restrict__ w_rest, const float* __restrict__ root_rest) {
    int i = blockIdx.x * blockDim.x + threadIdx.x;
    if (i >= 5 * WR_ELEMS) return;
    int l5 = i / WR_ELEMS;
    int rem = i - l5 * WR_ELEMS;
    int n = rem >> 8, k = rem & 255;
    float v = (n < NR * DH)
        ? w_rest[(((size_t)l5 * NR + (n >> 8)) * DH + k) * DH + (n & 255)]
        : root_rest[((size_t)l5 * DH + k) * DH + (n - NR * DH)];
    __nv_bfloat16 h, l; split_bf16(v, h, l);
    g_wth[W0_ELEMS + i] = h; g_wtl[W0_ELEMS + i] = l;
}

// ---------------- small utility kernels ----------------
__global__ void zero_cnt_kernel() {
    int i = blockIdx.x * blockDim.x + threadIdx.x;
    if (i < NR * NN) g_cnt[i] = 0.f;
}
__global__ void count_edges_kernel() {
    int e = blockIdx.x * blockDim.x + threadIdx.x;
    if (e >= NE) return;
    atomicAdd(&g_cnt[g_rel[e] * NN + g_dst[e]], 1.f);
}
__global__ void make_inv_kernel() {
    int i = blockIdx.x * blockDim.x + threadIdx.x;
    if (i < NR * NN) g_invcnt[i] = 1.f / fmaxf(g_cnt[i], 1.f);
}
__global__ void zero_pool_kernel() {
    int i = blockIdx.x * blockDim.x + threadIdx.x;
    if (i < NG * DH) { g_psum[i] = 0.f; g_pmax[i] = 0; }
    if (i < NG) g_gcnt[i] = 0.f;
}

// ---------------- mma.sync GEMM, cp.async double-buffered ----------------
// C[60000 x 1280] = A[60000 x K] @ [W0|W1|W2|W3|root]^T, 3-pass bf16 hi/lo.
// Block tile 128x128x32, 8 warps (2m x 4n), warp tile 64x32. Smem rows padded to
// SP=40 bf16 (80B stride -> ldmatrix conflict-free; 16B-aligned for cp.async).
// Inner loop is B-stationary per k16-step to keep live regs ~88 (no spills @128cap).
#define SP 40
#define STG_BYTES (4 * 128 * SP * 2)      // 40960 per stage
#define BUF_BYTES (128 * SP * 2)          // 10240 per buffer
#define GSMEM_TOTAL (2 * STG_BYTES)

__global__ __launch_bounds__(256, 2) void gemm_mma(int layer, const float* __restrict__ bias)
{
    extern __shared__ char dsm[];
    const uint32_t sb = smem_to_u32(dsm);

    const int K = layer ? DH : DIN;
    const size_t boff = layer ? (size_t)W0_ELEMS + (size_t)(layer - 1) * WR_ELEMS : 0;
    const __nv_bfloat16* __restrict__ Ah = layer ? (const __nv_bfloat16*)g_hbh : (const __nv_bfloat16*)g_xh;
    const __nv_bfloat16* __restrict__ Al = layer ? (const __nv_bfloat16*)g_hbl : (const __nv_bfloat16*)g_xl;
    const __nv_bfloat16* __restrict__ Bh = (const __nv_bfloat16*)g_wth + boff;
    const __nv_bfloat16* __restrict__ Bl = (const __nv_bfloat16*)g_wtl + boff;

    const int bm = blockIdx.x * 128;
    const int cn = blockIdx.y * 128;

    const int tid = threadIdx.x, lane = tid & 31, wid = tid >> 5;
    const int m_warp = (wid >> 2) * 64, n_warp = (wid & 3) * 32;

    float acc[4][4][4] = {};

    // per-thread load coords (8 x cp.async of 16B per stage: 2 iters x 4 buffers)
    const int l_r0 = tid >> 2;            // 0..63
    const int l_c8 = tid & 3;             // 16B chunk within 64B row-chunk
    const uint32_t so0 = (uint32_t)(l_r0 * SP + l_c8 * 8) * 2;
    const uint32_t so1 = (uint32_t)((l_r0 + 64) * SP + l_c8 * 8) * 2;

    // ldmatrix per-lane address components
    const int a_row = lane & 15;
    const int a_kb  = (lane >> 4) << 4;
    const int bg    = lane >> 3;
    const int b_row = ((bg & 2) << 2) + (lane & 7);
    const int b_kb  = (bg & 1) << 4;

    const int nch = K >> 5;

    auto load_stage = [&](int st, int k0) {
        const uint32_t s0 = sb + st * STG_BYTES;
        size_t ga0 = (size_t)(bm + l_r0) * K + k0 + l_c8 * 8;
        size_t gb0 = (size_t)(cn + l_r0) * K + k0 + l_c8 * 8;
        size_t ga1 = ga0 + (size_t)64 * K;
        size_t gb1 = gb0 + (size_t)64 * K;
        cpasync16(s0 + 0 * BUF_BYTES + so0, Ah + ga0);
        cpasync16(s0 + 1 * BUF_BYTES + so0, Al + ga0);
        cpasync16(s0 + 2 * BUF_BYTES + so0, Bh + gb0);
        cpasync16(s0 + 3 * BUF_BYTES + so0, Bl + gb0);
        cpasync16(s0 + 0 * BUF_BYTES + so1, Ah + ga1);
        cpasync16(s0 + 1 * BUF_BYTES + so1, Al + ga1);
        cpasync16(s0 + 2 * BUF_BYTES + so1, Bh + gb1);
        cpasync16(s0 + 3 * BUF_BYTES + so1, Bl + gb1);
    };

    load_stage(0, 0);
    CP_COMMIT();

    for (int c = 0; c < nch; c++) {
        const bool more = (c + 1 < nch);
        if (more) { load_stage((c + 1) & 1, (c + 1) << 5); CP_COMMIT(); }
        if (more) CP_WAIT1(); else CP_WAIT0();
        __syncthreads();

        const uint32_t s0  = sb + (c & 1) * STG_BYTES;
        const uint32_t aAh = s0;
        const uint32_t aAl = s0 + 1 * BUF_BYTES;
        const uint32_t aBh = s0 + 2 * BUF_BYTES;
        const uint32_t aBl = s0 + 3 * BUF_BYTES;

        #pragma unroll
        for (int s = 0; s < 2; s++) {
            const int akoff = s * 32 + a_kb;   // bytes within 80B row
            const int bkoff = s * 32 + b_kb;
            // B fragments for this k16-step (stationary across mi)
            uint32_t bh[2][4], bl[2][4];
            #pragma unroll
            for (int nb = 0; nb < 2; nb++) {
                uint32_t boffs = (uint32_t)(n_warp + nb * 16 + b_row) * (SP * 2) + bkoff;
                ldsm4(bh[nb][0], bh[nb][1], bh[nb][2], bh[nb][3], aBh + boffs);
                ldsm4(bl[nb][0], bl[nb][1], bl[nb][2], bl[nb][3], aBl + boffs);
            }
            #pragma unroll
            for (int mi = 0; mi < 4; mi++) {
                uint32_t off = (uint32_t)(m_warp + mi * 16 + a_row) * (SP * 2) + akoff;
                uint32_t ah[4], al[4];
                ldsm4(ah[0], ah[1], ah[2], ah[3], aAh + off);
                ldsm4(al[0], al[1], al[2], al[3], aAl + off);
                #pragma unroll
                for (int nb = 0; nb < 2; nb++)
                    #pragma unroll
                    for (int nj = 0; nj < 2; nj++) {
                        float* d = acc[mi][nb * 2 + nj];
                        mma16816(d, ah, bh[nb][2 * nj], bh[nb][2 * nj + 1]);
                        mma16816(d, al, bh[nb][2 * nj], bh[nb][2 * nj + 1]);
                        mma16816(d, ah, bl[nb][2 * nj], bl[nb][2 * nj + 1]);
                    }
            }
        }
        __syncthreads();
    }

    // epilogue: c0,c1 -> (row, col), c2,c3 -> (row+8, col)
    const bool isRoot = (cn >= NR * DH);
    const int rel = cn >> 8;
    const int cb128 = cn & 255;
    #pragma unroll
    for (int mi = 0; mi < 4; mi++) {
        int r0 = bm + m_warp + mi * 16 + (lane >> 2);
        #pragma unroll
        for (int half = 0; half < 2; half++) {
            int r = r0 + half * 8;
            if (r >= NN) continue;
            #pragma unroll
            for (int nj = 0; nj < 4; nj++) {
                int c = n_warp + nj * 8 + (lane & 3) * 2;
                float v0 = acc[mi][nj][half * 2 + 0];
                float v1 = acc[mi][nj][half * 2 + 1];
                if (isRoot) {
                    int col = (cn - NR * DH) + c;
                    float2 o = make_float2(v0 + bias[col], v1 + bias[col + 1]);
                    *(float2*)(g_acc + (size_t)r * DH + col) = o;
                } else {
                    *(float2*)(g_y + ((size_t)rel * NN + r) * DH + cb128 + c) = make_float2(v0, v1);
                }
            }
        }
    }
}

// ---------------- edge scatter: acc[dst] += y[rel][src] * invcnt[rel][dst] ----------------
__global__ __launch_bounds__(256) void edge_scatter() {
    int e = blockIdx.x * 8 + (threadIdx.x >> 5);
    if (e >= NE) return;
    int lane = threadIdx.x & 31;
    int src = g_src[e];
    int dst = g_dst[e];
    int rel = g_rel[e];
    float inv = g_invcnt[rel * NN + dst];
    const float4* ys = (const float4*)(g_y + ((size_t)rel * NN + src) * DH);
    float* ad = g_acc + (size_t)dst * DH;
    #pragma unroll
    for (int i = 0; i < 2; i++) {
        float4 v = ys[lane + 32 * i];
        red4(ad + (lane + 32 * i) * 4, v.x * inv, v.y * inv, v.z * inv, v.w * inv);
    }
}

// ---------------- relu + bf16 split for next layer (8 elems/thread) ----------------
__global__ void relu_bf_kernel(int writeF32) {
    int i = blockIdx.x * blockDim.x + threadIdx.x;
    if (i >= NN * DH / 8) return;
    const float4* p = (const float4*)g_acc + (size_t)i * 2;
    float4 v0 = p[0], v1 = p[1];
    float vv[8] = {v0.x, v0.y, v0.z, v0.w, v1.x, v1.y, v1.z, v1.w};
    union { __nv_bfloat16 b[8]; uint4 u; } H, L;
    #pragma unroll
    for (int j = 0; j < 8; j++) {
        vv[j] = fmaxf(vv[j], 0.f);
        split_bf16(vv[j], H.b[j], L.b[j]);
    }
    ((uint4*)g_hbh)[i] = H.u;
    ((uint4*)g_hbl)[i] = L.u;
    if (writeF32) {
        float4* q = (float4*)g_h + (size_t)i * 2;
        q[0] = make_float4(vv[0], vv[1], vv[2], vv[3]);
        q[1] = make_float4(vv[4], vv[5], vv[6], vv[7]);
    }
}

// ---------------- graph pooling (sum + max + count) ----------------
__global__ void pool_kernel() {
    int idx = blockIdx.x * blockDim.x + threadIdx.x;
    if (idx >= NN * DH) return;
    int node = idx >> 8;
    int d    = idx & (DH - 1);
    int g    = g_bat[node];
    float v  = g_h[idx];
    atomicAdd(&g_psum[g * DH + d], v);
    atomicMax(&g_pmax[g * DH + d], __float_as_int(v));
    if (d == 0) atomicAdd(&g_gcnt[g], 1.f);
}

// ---------------- final MLP head ----------------
__global__ __launch_bounds__(128) void mlp_kernel(
    const float* __restrict__ fc1w, const float* __restrict__ fc1b,
    const float* __restrict__ fc2w, const float* __restrict__ fc2b,
    float* __restrict__ out)
{
    __shared__ float gv[2 * DH];
    __shared__ float partial[4];
    int gi = blockIdx.x;
    int t  = threadIdx.x;
    float cnt = fmaxf(g_gcnt[gi], 1.f);
    for (int i = t; i < DH; i += 128) {
        gv[i]      = g_psum[gi * DH + i] / cnt;
        gv[DH + i] = __int_as_float(g_pmax[gi * DH + i]);
    }
    __syncthreads();
    float a = fc1b[t];
    #pragma unroll 8
    for (int i = 0; i < 2 * DH; i++) a += gv[i] * fc1w[i * 128 + t];
    a = fmaxf(a, 0.f);
    float p = a * fc2w[t];
    #pragma unroll
    for (int o = 16; o > 0; o >>= 1) p += __shfl_down_sync(0xffffffffu, p, o);
    if ((t & 31) == 0) partial[t >> 5] = p;
    __syncthreads();
    if (t == 0) {
        float s = partial[0] + partial[1] + partial[2] + partial[3] + fc2b[0];
        out[gi] = 1.f / (1.f + expf(-s));
    }
}

// ---------------- launch ----------------
extern "C" void kernel_launch(void* const* d_in, const int* in_sizes, int n_in,
                              void* d_out, int out_size)
{
    const float* x         = (const float*)d_in[0];
    const void*  ei        = d_in[1];
    const void*  ea        = d_in[2];
    const void*  ba        = d_in[3];
    const float* w0        = (const float*)d_in[4];
    const float* root0     = (const float*)d_in[5];
    const float* b0        = (const float*)d_in[6];
    const float* w_rest    = (const float*)d_in[7];
    const float* root_rest = (const float*)d_in[8];
    const float* b_rest    = (const float*)d_in[9];
    const float* fc1w      = (const float*)d_in[10];
    const float* fc1b      = (const float*)d_in[11];
    const float* fc2w      = (const float*)d_in[12];
    const float* fc2b      = (const float*)d_in[13];
    float* out = (float*)d_out;

    const int T = 256;

    cudaFuncSetAttribute(gemm_mma, cudaFuncAttributeMaxDynamicSharedMemorySize, GSMEM_TOTAL);

    dim3 ggrid((NN + 127) / 128, 10);
    const int egrid = (NE + 7) / 8;
    const int rgrid8 = (NN * DH / 8 + T - 1) / T;

    // conversions first so gemm_mma(layer 0) is the 4th launch (ncu -s 5 target)
    cvt_x_kernel<<<(NN * DIN / 8 + T - 1) / T, T>>>(x);
    cvt_w0_kernel<<<(W0_ELEMS + T - 1) / T, T>>>(w0, root0);
    cvt_wrest_kernel<<<(5 * WR_ELEMS + T - 1) / T, T>>>(w_rest, root_rest);

    gemm_mma<<<ggrid, 256, GSMEM_TOTAL>>>(0, b0);   // layer 0 GEMM (profiled launch)

    // index decode + normalizers (needed before first edge_scatter)
    detect_kernel<<<1, 256>>>((const unsigned*)ei, (const unsigned*)ea, (const unsigned*)ba);
    cvt_edges_kernel<<<(NE + T - 1) / T, T>>>(ei, ea);
    cvt_batch_kernel<<<(NN + T - 1) / T, T>>>(ba);
    zero_cnt_kernel<<<(NR * NN + T - 1) / T, T>>>();
    count_edges_kernel<<<(NE + T - 1) / T, T>>>();
    make_inv_kernel<<<(NR * NN + T - 1) / T, T>>>();

    edge_scatter<<<egrid, 256>>>();
    relu_bf_kernel<<<rgrid8, T>>>(0);

    for (int l = 1; l < NL; l++) {
        gemm_mma<<<ggrid, 256, GSMEM_TOTAL>>>(l, b_rest + (size_t)(l - 1) * DH);
        edge_scatter<<<egrid, 256>>>();
        relu_bf_kernel<<<rgrid8, T>>>(l == NL - 1 ? 1 : 0);
    }

    zero_pool_kernel<<<(NG * DH + T - 1) / T, T>>>();
    pool_kernel<<<(NN * DH + T - 1) / T, T>>>();
    mlp_kernel<<<NG, 128>>>(fc1w, fc1b, fc2w, fc2b, out);
}

// round 14
// speedup vs baseline: 3.0455x; 1.2085x over previous
#include <cuda_runtime.h>
#include <cuda_fp16.h>
#include <math.h>
#include <stdint.h>

#define NN 60000
#define NNP 60128          // padded rows (tile overrun safe)
#define NE 240000
#define NR 4
#define NG 128
#define DIN 768
#define DH 256
#define NL 6

// ---------------- scratch (static device globals; no allocation) ----------------
__device__ __align__(16) float g_h[(size_t)NN * DH];          // fp32 activations (for pooling)
__device__ __align__(16) float g_acc[(size_t)NN * DH];        // root transform + edge accumulation
__device__ __align__(16) float g_y[(size_t)NR * NN * DH];     // per-relation transformed features
__device__ __align__(16) float g_cnt[NR * NN];
__device__ __align__(16) float g_invcnt[NR * NN];
__device__ __align__(16) float g_psum[NG * DH];
__device__ __align__(16) int   g_pmax[NG * DH];
__device__ __align__(16) float g_gcnt[NG];

// fp16 hi/lo split activations for tensor-core GEMMs (A side exact to ~22 bits)
__device__ __align__(16) __half g_xh[(size_t)NNP * DIN];
__device__ __align__(16) __half g_xl[(size_t)NNP * DIN];
__device__ __align__(16) __half g_hbh[(size_t)NNP * DH];
__device__ __align__(16) __half g_hbl[(size_t)NNP * DH];
// transposed weights (single fp16): layer0 [1280][768] then layers1-5 [1280][256]
#define W0_ELEMS (1280 * 768)
#define WR_ELEMS (1280 * 256)
#define WT_TOTAL (W0_ELEMS + 5 * WR_ELEMS)
__device__ __align__(16) __half g_wt[WT_TOTAL];

// decoded int32 index arrays + dtype flags
__device__ int g_src[NE];
__device__ int g_dst[NE];
__device__ int g_rel[NE];
__device__ int g_bat[NN];
__device__ int g_is64_ei, g_is64_ea, g_is64_b;

// ---------------- helpers ----------------
__device__ __forceinline__ uint32_t smem_to_u32(const void* p) {
    uint32_t a;
    asm("{ .reg .u64 t; cvta.to.shared.u64 t, %1; cvt.u32.u64 %0, t; }" : "=r"(a) : "l"(p));
    return a;
}

__device__ __forceinline__ void ldsm4(uint32_t& r0, uint32_t& r1, uint32_t& r2, uint32_t& r3, uint32_t addr) {
    asm volatile("ldmatrix.sync.aligned.m8n8.x4.shared.b16 {%0,%1,%2,%3}, [%4];"
                 : "=r"(r0), "=r"(r1), "=r"(r2), "=r"(r3) : "r"(addr));
}

__device__ __forceinline__ void mma16816(float* d, const uint32_t* a, uint32_t b0, uint32_t b1) {
    asm volatile("mma.sync.aligned.m16n8k16.row.col.f32.f16.f16.f32 "
                 "{%0,%1,%2,%3}, {%4,%5,%6,%7}, {%8,%9}, {%0,%1,%2,%3};"
                 : "+f"(d[0]), "+f"(d[1]), "+f"(d[2]), "+f"(d[3])
                 : "r"(a[0]), "r"(a[1]), "r"(a[2]), "r"(a[3]), "r"(b0), "r"(b1));
}

__device__ __forceinline__ void cpasync16(uint32_t saddr, const void* gaddr) {
    asm volatile("cp.async.cg.shared.global [%0], [%1], 16;" :: "r"(saddr), "l"(gaddr));
}
#define CP_COMMIT() asm volatile("cp.async.commit_group;" ::: "memory")
#define CP_WAIT0()  asm volatile("cp.async.wait_group 0;" ::: "memory")
#define CP_WAIT1()  asm volatile("cp.async.wait_group 1;" ::: "memory")

__device__ __forceinline__ void red4(float* p, float a, float b, float c, float d) {
    asm volatile("red.global.add.v4.f32 [%0], {%1,%2,%3,%4};"
                 :: "l"(p), "f"(a), "f"(b), "f"(c), "f"(d) : "memory");
}

__device__ __forceinline__ void split_fp16(float v, __half& hi, __half& lo) {
    hi = __float2half(v);
    lo = __float2half(v - __half2float(hi));
}

// ---------------- dtype detection ----------------
__global__ void detect_kernel(const unsigned* __restrict__ ei,
                              const unsigned* __restrict__ ea,
                              const unsigned* __restrict__ ba) {
    __shared__ int s[3];
    int t = threadIdx.x;
    if (t < 3) s[t] = 1;
    __syncthreads();
    { unsigned w = ei[2 * (t * 937) + 1]; if (w != 0) atomicAnd(&s[0], 0); }
    { unsigned w = ea[2 * (t * 468) + 1]; if (w != 0) atomicAnd(&s[1], 0); }
    { unsigned w = ba[2 * (t * 117) + 1]; if (w != 0) atomicAnd(&s[2], 0); }
    __syncthreads();
    if (t == 0) { g_is64_ei = s[0]; g_is64_ea = s[1]; g_is64_b = s[2]; }
}

__global__ void cvt_edges_kernel(const void* __restrict__ ei, const void* __restrict__ ea) {
    int e = blockIdx.x * blockDim.x + threadIdx.x;
    if (e >= NE) return;
    long long s, d, r;
    if (g_is64_ei) { const long long* p = (const long long*)ei; s = p[e]; d = p[NE + e]; }
    else           { const int* p = (const int*)ei;             s = p[e]; d = p[NE + e]; }
    if (g_is64_ea) r = ((const long long*)ea)[e];
    else           r = ((const int*)ea)[e];
    g_src[e] = (int)(s < 0 ? 0 : (s >= NN ? NN - 1 : s));
    g_dst[e] = (int)(d < 0 ? 0 : (d >= NN ? NN - 1 : d));
    g_rel[e] = (int)(r & 3);
}

__global__ void cvt_batch_kernel(const void* __restrict__ ba) {
    int i = blockIdx.x * blockDim.x + threadIdx.x;
    if (i >= NN) return;
    long long b = g_is64_b ? ((const long long*)ba)[i] : (long long)((const int*)ba)[i];
    g_bat[i] = (int)(b < 0 ? 0 : (b >= NG ? NG - 1 : b));
}

// ---------------- fp16 hi/lo conversions (vectorized: 8 elems/thread) ----------------
__global__ void cvt_x_kernel(const float* __restrict__ x) {
    int i = blockIdx.x * blockDim.x + threadIdx.x;
    if (i >= NN * DIN / 8) return;
    const float4* p = (const float4*)x + (size_t)i * 2;
    float4 v0 = p[0], v1 = p[1];
    float vv[8] = {v0.x, v0.y, v0.z, v0.w, v1.x, v1.y, v1.z, v1.w};
    union { __half b[8]; uint4 u; } H, L;
    #pragma unroll
    for (int j = 0; j < 8; j++) split_fp16(vv[j], H.b[j], L.b[j]);
    ((uint4*)g_xh)[i] = H.u;
    ((uint4*)g_xl)[i] = L.u;
}

// layer0 weights transposed: g_wt[n][k], n in [0,1280), k in [0,768)
__global__ void cvt_w0_kernel(const float* __restrict__ w0, const float* __restrict__ root0) {
    int i = blockIdx.x * blockDim.x + threadIdx.x;
    if (i >= W0_ELEMS) return;
    int n = i / DIN, k = i - n * DIN;
    float v = (n < NR * DH) ? w0[((size_t)(n >> 8) * DIN + k) * DH + (n & 255)]
                            : root0[(size_t)k * DH + (n - NR * DH)];
    g_wt[i] = __float2half(v);
}

// layers 1..5: g_wt[W0 + l5*WR + n*256 + k]
__global__ void cvt_wrest_kernel(const float* __restrict__ w_rest, const float* __restrict__ root_rest) {
    int i = blockIdx.x * blockDim.x + threadIdx.x;
    if (i >= 5 * WR_ELEMS) return;
    int l5 = i / WR_ELEMS;
    int rem = i - l5 * WR_ELEMS;
    int n = rem >> 8, k = rem & 255;
    float v = (n < NR * DH)
        ? w_rest[(((size_t)l5 * NR + (n >> 8)) * DH + k) * DH + (n & 255)]
        : root_rest[((size_t)l5 * DH + k) * DH + (n - NR * DH)];
    g_wt[W0_ELEMS + i] = __float2half(v);
}

// ---------------- small utility kernels ----------------
__global__ void zero_cnt_kernel() {
    int i = blockIdx.x * blockDim.x + threadIdx.x;
    if (i < NR * NN) g_cnt[i] = 0.f;
}
__global__ void count_edges_kernel() {
    int e = blockIdx.x * blockDim.x + threadIdx.x;
    if (e >= NE) return;
    atomicAdd(&g_cnt[g_rel[e] * NN + g_dst[e]], 1.f);
}
__global__ void make_inv_kernel() {
    int i = blockIdx.x * blockDim.x + threadIdx.x;
    if (i < NR * NN) g_invcnt[i] = 1.f / fmaxf(g_cnt[i], 1.f);
}
__global__ void zero_pool_kernel() {
    int i = blockIdx.x * blockDim.x + threadIdx.x;
    if (i < NG * DH) { g_psum[i] = 0.f; g_pmax[i] = 0; }
    if (i < NG) g_gcnt[i] = 0.f;
}

// ---------------- mma.sync GEMM, cp.async double-buffered, fp16 2-pass ----------------
// C[60000 x 1280] = A[60000 x K] @ [W0|W1|W2|W3|root]^T.
// A = Ah + Al (fp16 split, exact to ~22 bits); B single fp16 (error 2^-12).
// Block tile 128x128x32, 8 warps (2m x 4n), warp tile 64x32. Smem rows padded to
// SP=40 halfs (80B stride -> ldmatrix conflict-free; 16B-aligned for cp.async).
#define SP 40
#define BUF_BYTES (128 * SP * 2)          // 10240 per buffer
#define STG_BYTES (3 * BUF_BYTES)         // Ah, Al, B = 30720 per stage
#define GSMEM_TOTAL (2 * STG_BYTES)       // 61440

__global__ __launch_bounds__(256, 2) void gemm_mma(int layer, const float* __restrict__ bias)
{
    extern __shared__ char dsm[];
    const uint32_t sb = smem_to_u32(dsm);

    const int K = layer ? DH : DIN;
    const size_t boff = layer ? (size_t)W0_ELEMS + (size_t)(layer - 1) * WR_ELEMS : 0;
    const __half* __restrict__ Ah = layer ? (const __half*)g_hbh : (const __half*)g_xh;
    const __half* __restrict__ Al = layer ? (const __half*)g_hbl : (const __half*)g_xl;
    const __half* __restrict__ Bp = (const __half*)g_wt + boff;

    const int bm = blockIdx.x * 128;
    const int cn = blockIdx.y * 128;

    const int tid = threadIdx.x, lane = tid & 31, wid = tid >> 5;
    const int m_warp = (wid >> 2) * 64, n_warp = (wid & 3) * 32;

    float acc[4][4][4] = {};

    // per-thread load coords (6 x cp.async of 16B per stage: 2 row-halves x 3 buffers)
    const int l_r0 = tid >> 2;            // 0..63
    const int l_c8 = tid & 3;             // 16B chunk within 64B row-chunk
    const uint32_t so0 = (uint32_t)(l_r0 * SP + l_c8 * 8) * 2;
    const uint32_t so1 = (uint32_t)((l_r0 + 64) * SP + l_c8 * 8) * 2;

    // ldmatrix per-lane address components
    const int a_row = lane & 15;
    const int a_kb  = (lane >> 4) << 4;
    const int bg    = lane >> 3;
    const int b_row = ((bg & 2) << 2) + (lane & 7);
    const int b_kb  = (bg & 1) << 4;

    const int nch = K >> 5;

    auto load_stage = [&](int st, int k0) {
        const uint32_t s0 = sb + st * STG_BYTES;
        size_t ga0 = (size_t)(bm + l_r0) * K + k0 + l_c8 * 8;
        size_t gb0 = (size_t)(cn + l_r0) * K + k0 + l_c8 * 8;
        size_t ga1 = ga0 + (size_t)64 * K;
        size_t gb1 = gb0 + (size_t)64 * K;
        cpasync16(s0 + 0 * BUF_BYTES + so0, Ah + ga0);
        cpasync16(s0 + 1 * BUF_BYTES + so0, Al + ga0);
        cpasync16(s0 + 2 * BUF_BYTES + so0, Bp + gb0);
        cpasync16(s0 + 0 * BUF_BYTES + so1, Ah + ga1);
        cpasync16(s0 + 1 * BUF_BYTES + so1, Al + ga1);
        cpasync16(s0 + 2 * BUF_BYTES + so1, Bp + gb1);
    };

    load_stage(0, 0);
    CP_COMMIT();

    for (int c = 0; c < nch; c++) {
        const bool more = (c + 1 < nch);
        if (more) { load_stage((c + 1) & 1, (c + 1) << 5); CP_COMMIT(); }
        if (more) CP_WAIT1(); else CP_WAIT0();
        __syncthreads();

        const uint32_t s0  = sb + (c & 1) * STG_BYTES;
        const uint32_t aAh = s0;
        const uint32_t aAl = s0 + 1 * BUF_BYTES;
        const uint32_t aB  = s0 + 2 * BUF_BYTES;

        #pragma unroll
        for (int s = 0; s < 2; s++) {
            const int akoff = s * 32 + a_kb;   // bytes within 80B row
            const int bkoff = s * 32 + b_kb;
            // B fragments for this k16-step (stationary across mi)
            uint32_t bh[2][4];
            #pragma unroll
            for (int nb = 0; nb < 2; nb++) {
                uint32_t boffs = (uint32_t)(n_warp + nb * 16 + b_row) * (SP * 2) + bkoff;
                ldsm4(bh[nb][0], bh[nb][1], bh[nb][2], bh[nb][3], aB + boffs);
            }
            #pragma unroll
            for (int mi = 0; mi < 4; mi++) {
                uint32_t off = (uint32_t)(m_warp + mi * 16 + a_row) * (SP * 2) + akoff;
                uint32_t ah[4], al[4];
                ldsm4(ah[0], ah[1], ah[2], ah[3], aAh + off);
                ldsm4(al[0], al[1], al[2], al[3], aAl + off);
                #pragma unroll
                for (int nb = 0; nb < 2; nb++)
                    #pragma unroll
                    for (int nj = 0; nj < 2; nj++) {
                        float* d = acc[mi][nb * 2 + nj];
                        mma16816(d, ah, bh[nb][2 * nj], bh[nb][2 * nj + 1]);
                        mma16816(d, al, bh[nb][2 * nj], bh[nb][2 * nj + 1]);
                    }
            }
        }
        __syncthreads();
    }

    // epilogue: c0,c1 -> (row, col), c2,c3 -> (row+8, col)
    const bool isRoot = (cn >= NR * DH);
    const int rel = cn >> 8;
    const int cb128 = cn & 255;
    #pragma unroll
    for (int mi = 0; mi < 4; mi++) {
        int r0 = bm + m_warp + mi * 16 + (lane >> 2);
        #pragma unroll
        for (int half = 0; half < 2; half++) {
            int r = r0 + half * 8;
            if (r >= NN) continue;
            #pragma unroll
            for (int nj = 0; nj < 4; nj++) {
                int c = n_warp + nj * 8 + (lane & 3) * 2;
                float v0 = acc[mi][nj][half * 2 + 0];
                float v1 = acc[mi][nj][half * 2 + 1];
                if (isRoot) {
                    int col = (cn - NR * DH) + c;
                    float2 o = make_float2(v0 + bias[col], v1 + bias[col + 1]);
                    *(float2*)(g_acc + (size_t)r * DH + col) = o;
                } else {
                    *(float2*)(g_y + ((size_t)rel * NN + r) * DH + cb128 + c) = make_float2(v0, v1);
                }
            }
        }
    }
}

// ---------------- edge scatter: acc[dst] += y[rel][src] * invcnt[rel][dst] ----------------
__global__ __launch_bounds__(256) void edge_scatter() {
    int e = blockIdx.x * 8 + (threadIdx.x >> 5);
    if (e >= NE) return;
    int lane = threadIdx.x & 31;
    int src = g_src[e];
    int dst = g_dst[e];
    int rel = g_rel[e];
    float inv = g_invcnt[rel * NN + dst];
    const float4* ys = (const float4*)(g_y + ((size_t)rel * NN + src) * DH);
    float* ad = g_acc + (size_t)dst * DH;
    #pragma unroll
    for (int i = 0; i < 2; i++) {
        float4 v = ys[lane + 32 * i];
        red4(ad + (lane + 32 * i) * 4, v.x * inv, v.y * inv, v.z * inv, v.w * inv);
    }
}

// ---------------- relu + fp16 split for next layer (8 elems/thread) ----------------
__global__ void relu_bf_kernel(int writeF32) {
    int i = blockIdx.x * blockDim.x + threadIdx.x;
    if (i >= NN * DH / 8) return;
    const float4* p = (const float4*)g_acc + (size_t)i * 2;
    float4 v0 = p[0], v1 = p[1];
    float vv[8] = {v0.x, v0.y, v0.z, v0.w, v1.x, v1.y, v1.z, v1.w};
    union { __half b[8]; uint4 u; } H, L;
    #pragma unroll
    for (int j = 0; j < 8; j++) {
        vv[j] = fmaxf(vv[j], 0.f);
        split_fp16(vv[j], H.b[j], L.b[j]);
    }
    ((uint4*)g_hbh)[i] = H.u;
    ((uint4*)g_hbl)[i] = L.u;
    if (writeF32) {
        float4* q = (float4*)g_h + (size_t)i * 2;
        q[0] = make_float4(vv[0], vv[1], vv[2], vv[3]);
        q[1] = make_float4(vv[4], vv[5], vv[6], vv[7]);
    }
}

// ---------------- graph pooling (sum + max + count) ----------------
__global__ void pool_kernel() {
    int idx = blockIdx.x * blockDim.x + threadIdx.x;
    if (idx >= NN * DH) return;
    int node = idx >> 8;
    int d    = idx & (DH - 1);
    int g    = g_bat[node];
    float v  = g_h[idx];
    atomicAdd(&g_psum[g * DH + d], v);
    atomicMax(&g_pmax[g * DH + d], __float_as_int(v));
    if (d == 0) atomicAdd(&g_gcnt[g], 1.f);
}

// ---------------- final MLP head ----------------
__global__ __launch_bounds__(128) void mlp_kernel(
    const float* __restrict__ fc1w, const float* __restrict__ fc1b,
    const float* __restrict__ fc2w, const float* __restrict__ fc2b,
    float* __restrict__ out)
{
    __shared__ float gv[2 * DH];
    __shared__ float partial[4];
    int gi = blockIdx.x;
    int t  = threadIdx.x;
    float cnt = fmaxf(g_gcnt[gi], 1.f);
    for (int i = t; i < DH; i += 128) {
        gv[i]      = g_psum[gi * DH + i] / cnt;
        gv[DH + i] = __int_as_float(g_pmax[gi * DH + i]);
    }
    __syncthreads();
    float a = fc1b[t];
    #pragma unroll 8
    for (int i = 0; i < 2 * DH; i++) a += gv[i] * fc1w[i * 128 + t];
    a = fmaxf(a, 0.f);
    float p = a * fc2w[t];
    #pragma unroll
    for (int o = 16; o > 0; o >>= 1) p += __shfl_down_sync(0xffffffffu, p, o);
    if ((t & 31) == 0) partial[t >> 5] = p;
    __syncthreads();
    if (t == 0) {
        float s = partial[0] + partial[1] + partial[2] + partial[3] + fc2b[0];
        out[gi] = 1.f / (1.f + expf(-s));
    }
}

// ---------------- launch ----------------
extern "C" void kernel_launch(void* const* d_in, const int* in_sizes, int n_in,
                              void* d_out, int out_size)
{
    const float* x         = (const float*)d_in[0];
    const void*  ei        = d_in[1];
    const void*  ea        = d_in[2];
    const void*  ba        = d_in[3];
    const float* w0        = (const float*)d_in[4];
    const float* root0     = (const float*)d_in[5];
    const float* b0        = (const float*)d_in[6];
    const float* w_rest    = (const float*)d_in[7];
    const float* root_rest = (const float*)d_in[8];
    const float* b_rest    = (const float*)d_in[9];
    const float* fc1w      = (const float*)d_in[10];
    const float* fc1b      = (const float*)d_in[11];
    const float* fc2w      = (const float*)d_in[12];
    const float* fc2b      = (const float*)d_in[13];
    float* out = (float*)d_out;

    const int T = 256;

    cudaFuncSetAttribute(gemm_mma, cudaFuncAttributeMaxDynamicSharedMemorySize, GSMEM_TOTAL);

    dim3 ggrid((NN + 127) / 128, 10);
    const int egrid = (NE + 7) / 8;
    const int rgrid8 = (NN * DH / 8 + T - 1) / T;

    // conversions first so gemm_mma(layer 0) is the 4th launch (ncu -s 5 target)
    cvt_x_kernel<<<(NN * DIN / 8 + T - 1) / T, T>>>(x);
    cvt_w0_kernel<<<(W0_ELEMS + T - 1) / T, T>>>(w0, root0);
    cvt_wrest_kernel<<<(5 * WR_ELEMS + T - 1) / T, T>>>(w_rest, root_rest);

    gemm_mma<<<ggrid, 256, GSMEM_TOTAL>>>(0, b0);   // layer 0 GEMM (profiled launch)

    // index decode + normalizers (needed before first edge_scatter)
    detect_kernel<<<1, 256>>>((const unsigned*)ei, (const unsigned*)ea, (const unsigned*)ba);
    cvt_edges_kernel<<<(NE + T - 1) / T, T>>>(ei, ea);
    cvt_batch_kernel<<<(NN + T - 1) / T, T>>>(ba);
    zero_cnt_kernel<<<(NR * NN + T - 1) / T, T>>>();
    count_edges_kernel<<<(NE + T - 1) / T, T>>>();
    make_inv_kernel<<<(NR * NN + T - 1) / T, T>>>();

    edge_scatter<<<egrid, 256>>>();
    relu_bf_kernel<<<rgrid8, T>>>(0);

    for (int l = 1; l < NL; l++) {
        gemm_mma<<<ggrid, 256, GSMEM_TOTAL>>>(l, b_rest + (size_t)(l - 1) * DH);
        edge_scatter<<<egrid, 256>>>();
        relu_bf_kernel<<<rgrid8, T>>>(l == NL - 1 ? 1 : 0);
    }

    zero_pool_kernel<<<(NG * DH + T - 1) / T, T>>>();
    pool_kernel<<<(NN * DH + T - 1) / T, T>>>();
    mlp_kernel<<<NG, 128>>>(fc1w, fc1b, fc2w, fc2b, out);
}

// round 15
// speedup vs baseline: 3.2204x; 1.0574x over previous
#include <cuda_runtime.h>
#include <cuda_fp16.h>
#include <math.h>
#include <stdint.h>

#define NN 60000
#define NNP 60128          // padded rows (tile overrun safe)
#define NE 240000
#define NR 4
#define NG 128
#define DIN 768
#define DH 256
#define NL 6

// ---------------- scratch (static device globals; no allocation) ----------------
__device__ __align__(16) float g_h[(size_t)NN * DH];          // fp32 activations (for pooling)
__device__ __align__(16) float g_acc[(size_t)NN * DH];        // root transform + edge accumulation
__device__ __align__(16) float g_y[(size_t)NR * NN * DH];     // per-relation transformed features
__device__ __align__(16) float g_cnt[NR * NN];
__device__ __align__(16) float g_invcnt[NR * NN];
__device__ __align__(16) float g_psum[NG * DH];
__device__ __align__(16) int   g_pmax[NG * DH];
__device__ __align__(16) float g_gcnt[NG];

// fp16 hi/lo split activations for tensor-core GEMMs (A side exact to ~22 bits)
__device__ __align__(16) __half g_xh[(size_t)NNP * DIN];
__device__ __align__(16) __half g_xl[(size_t)NNP * DIN];
__device__ __align__(16) __half g_hbh[(size_t)NNP * DH];
__device__ __align__(16) __half g_hbl[(size_t)NNP * DH];
// transposed weights (single fp16): layer0 [1280][768] then layers1-5 [1280][256]
#define W0_ELEMS (1280 * 768)
#define WR_ELEMS (1280 * 256)
#define WT_TOTAL (W0_ELEMS + 5 * WR_ELEMS)
__device__ __align__(16) __half g_wt[WT_TOTAL];

// decoded int32 index arrays + dtype flags
__device__ int g_src[NE];
__device__ int g_dst[NE];
__device__ int g_rel[NE];
__device__ int g_bat[NN];
__device__ int g_is64_ei, g_is64_ea, g_is64_b;

// ---------------- helpers ----------------
__device__ __forceinline__ uint32_t smem_to_u32(const void* p) {
    uint32_t a;
    asm("{ .reg .u64 t; cvta.to.shared.u64 t, %1; cvt.u32.u64 %0, t; }" : "=r"(a) : "l"(p));
    return a;
}

__device__ __forceinline__ void ldsm4(uint32_t& r0, uint32_t& r1, uint32_t& r2, uint32_t& r3, uint32_t addr) {
    asm volatile("ldmatrix.sync.aligned.m8n8.x4.shared.b16 {%0,%1,%2,%3}, [%4];"
                 : "=r"(r0), "=r"(r1), "=r"(r2), "=r"(r3) : "r"(addr));
}

__device__ __forceinline__ void mma16816(float* d, const uint32_t* a, uint32_t b0, uint32_t b1) {
    asm volatile("mma.sync.aligned.m16n8k16.row.col.f32.f16.f16.f32 "
                 "{%0,%1,%2,%3}, {%4,%5,%6,%7}, {%8,%9}, {%0,%1,%2,%3};"
                 : "+f"(d[0]), "+f"(d[1]), "+f"(d[2]), "+f"(d[3])
                 : "r"(a[0]), "r"(a[1]), "r"(a[2]), "r"(a[3]), "r"(b0), "r"(b1));
}

__device__ __forceinline__ void cpasync16(uint32_t saddr, const void* gaddr) {
    asm volatile("cp.async.cg.shared.global [%0], [%1], 16;" :: "r"(saddr), "l"(gaddr));
}
#define CP_COMMIT() asm volatile("cp.async.commit_group;" ::: "memory")
#define CP_WAIT0()  asm volatile("cp.async.wait_group 0;" ::: "memory")
#define CP_WAIT1()  asm volatile("cp.async.wait_group 1;" ::: "memory")

__device__ __forceinline__ void red4(float* p, float a, float b, float c, float d) {
    asm volatile("red.global.add.v4.f32 [%0], {%1,%2,%3,%4};"
                 :: "l"(p), "f"(a), "f"(b), "f"(c), "f"(d) : "memory");
}

__device__ __forceinline__ void split_fp16(float v, __half& hi, __half& lo) {
    hi = __float2half(v);
    lo = __float2half(v - __half2float(hi));
}

// ---------------- dtype detection ----------------
__global__ void detect_kernel(const unsigned* __restrict__ ei,
                              const unsigned* __restrict__ ea,
                              const unsigned* __restrict__ ba) {
    __shared__ int s[3];
    int t = threadIdx.x;
    if (t < 3) s[t] = 1;
    __syncthreads();
    { unsigned w = ei[2 * (t * 937) + 1]; if (w != 0) atomicAnd(&s[0], 0); }
    { unsigned w = ea[2 * (t * 468) + 1]; if (w != 0) atomicAnd(&s[1], 0); }
    { unsigned w = ba[2 * (t * 117) + 1]; if (w != 0) atomicAnd(&s[2], 0); }
    __syncthreads();
    if (t == 0) { g_is64_ei = s[0]; g_is64_ea = s[1]; g_is64_b = s[2]; }
}

__global__ void cvt_edges_kernel(const void* __restrict__ ei, const void* __restrict__ ea) {
    int e = blockIdx.x * blockDim.x + threadIdx.x;
    if (e >= NE) return;
    long long s, d, r;
    if (g_is64_ei) { const long long* p = (const long long*)ei; s = p[e]; d = p[NE + e]; }
    else           { const int* p = (const int*)ei;             s = p[e]; d = p[NE + e]; }
    if (g_is64_ea) r = ((const long long*)ea)[e];
    else           r = ((const int*)ea)[e];
    g_src[e] = (int)(s < 0 ? 0 : (s >= NN ? NN - 1 : s));
    g_dst[e] = (int)(d < 0 ? 0 : (d >= NN ? NN - 1 : d));
    g_rel[e] = (int)(r & 3);
}

__global__ void cvt_batch_kernel(const void* __restrict__ ba) {
    int i = blockIdx.x * blockDim.x + threadIdx.x;
    if (i >= NN) return;
    long long b = g_is64_b ? ((const long long*)ba)[i] : (long long)((const int*)ba)[i];
    g_bat[i] = (int)(b < 0 ? 0 : (b >= NG ? NG - 1 : b));
}

// ---------------- fp16 hi/lo conversions (vectorized: 8 elems/thread) ----------------
__global__ void cvt_x_kernel(const float* __restrict__ x) {
    int i = blockIdx.x * blockDim.x + threadIdx.x;
    if (i >= NN * DIN / 8) return;
    const float4* p = (const float4*)x + (size_t)i * 2;
    float4 v0 = p[0], v1 = p[1];
    float vv[8] = {v0.x, v0.y, v0.z, v0.w, v1.x, v1.y, v1.z, v1.w};
    union { __half b[8]; uint4 u; } H, L;
    #pragma unroll
    for (int j = 0; j < 8; j++) split_fp16(vv[j], H.b[j], L.b[j]);
    ((uint4*)g_xh)[i] = H.u;
    ((uint4*)g_xl)[i] = L.u;
}

// layer0 weights transposed: g_wt[n][k], n in [0,1280), k in [0,768)
__global__ void cvt_w0_kernel(const float* __restrict__ w0, const float* __restrict__ root0) {
    int i = blockIdx.x * blockDim.x + threadIdx.x;
    if (i >= W0_ELEMS) return;
    int n = i / DIN, k = i - n * DIN;
    float v = (n < NR * DH) ? w0[((size_t)(n >> 8) * DIN + k) * DH + (n & 255)]
                            : root0[(size_t)k * DH + (n - NR * DH)];
    g_wt[i] = __float2half(v);
}

// layers 1..5: g_wt[W0 + l5*WR + n*256 + k]
__global__ void cvt_wrest_kernel(const float* __restrict__ w_rest, const float* __restrict__ root_rest) {
    int i = blockIdx.x * blockDim.x + threadIdx.x;
    if (i >= 5 * WR_ELEMS) return;
    int l5 = i / WR_ELEMS;
    int rem = i - l5 * WR_ELEMS;
    int n = rem >> 8, k = rem & 255;
    float v = (n < NR * DH)
        ? w_rest[(((size_t)l5 * NR + (n >> 8)) * DH + k) * DH + (n & 255)]
        : root_rest[((size_t)l5 * DH + k) * DH + (n - NR * DH)];
    g_wt[W0_ELEMS + i] = __float2half(v);
}

// ---------------- small utility kernels ----------------
__global__ void zero_cnt_kernel() {
    int i = blockIdx.x * blockDim.x + threadIdx.x;
    if (i < NR * NN) g_cnt[i] = 0.f;
}
__global__ void count_edges_kernel() {
    int e = blockIdx.x * blockDim.x + threadIdx.x;
    if (e >= NE) return;
    atomicAdd(&g_cnt[g_rel[e] * NN + g_dst[e]], 1.f);
}
__global__ void make_inv_kernel() {
    int i = blockIdx.x * blockDim.x + threadIdx.x;
    if (i < NR * NN) g_invcnt[i] = 1.f / fmaxf(g_cnt[i], 1.f);
}
__global__ void zero_pool_kernel() {
    int i = blockIdx.x * blockDim.x + threadIdx.x;
    if (i < NG * DH) { g_psum[i] = 0.f; g_pmax[i] = 0; }
    if (i < NG) g_gcnt[i] = 0.f;
}

// ---------------- mma.sync GEMM, 3-stage cp.async pipeline, fp16 2-pass ----------------
// C[60000 x 1280] = A[60000 x K] @ [W0|W1|W2|W3|root]^T.
// A = Ah + Al (fp16 split, exact to ~22 bits); B single fp16.
// Block tile 128x128x32, 8 warps (2m x 4n), warp tile 64x32. Smem rows padded to
// SP=40 halfs (80B stride -> ldmatrix conflict-free). Single barrier per iter:
// load for stage c+2 targets the buffer consumed at iter c-1, which the top-of-
// loop barrier at iter c already protects.
#define SP 40
#define BUF_BYTES (128 * SP * 2)          // 10240 per buffer
#define STG_BYTES (3 * BUF_BYTES)         // Ah, Al, B = 30720 per stage
#define NSTG 3
#define GSMEM_TOTAL (NSTG * STG_BYTES)    // 92160

__global__ __launch_bounds__(256, 2) void gemm_mma(int layer, const float* __restrict__ bias)
{
    extern __shared__ char dsm[];
    const uint32_t sb = smem_to_u32(dsm);

    const int K = layer ? DH : DIN;
    const size_t boff = layer ? (size_t)W0_ELEMS + (size_t)(layer - 1) * WR_ELEMS : 0;
    const __half* __restrict__ Ah = layer ? (const __half*)g_hbh : (const __half*)g_xh;
    const __half* __restrict__ Al = layer ? (const __half*)g_hbl : (const __half*)g_xl;
    const __half* __restrict__ Bp = (const __half*)g_wt + boff;

    const int bm = blockIdx.x * 128;
    const int cn = blockIdx.y * 128;

    const int tid = threadIdx.x, lane = tid & 31, wid = tid >> 5;
    const int m_warp = (wid >> 2) * 64, n_warp = (wid & 3) * 32;

    float acc[4][4][4] = {};

    // per-thread load coords (6 x cp.async of 16B per stage: 2 row-halves x 3 buffers)
    const int l_r0 = tid >> 2;            // 0..63
    const int l_c8 = tid & 3;             // 16B chunk within 64B row-chunk
    const uint32_t so0 = (uint32_t)(l_r0 * SP + l_c8 * 8) * 2;
    const uint32_t so1 = (uint32_t)((l_r0 + 64) * SP + l_c8 * 8) * 2;

    // ldmatrix per-lane address components
    const int a_row = lane & 15;
    const int a_kb  = (lane >> 4) << 4;
    const int bg    = lane >> 3;
    const int b_row = ((bg & 2) << 2) + (lane & 7);
    const int b_kb  = (bg & 1) << 4;

    const int nch = K >> 5;

    auto load_stage = [&](int st, int k0) {
        const uint32_t s0 = sb + st * STG_BYTES;
        size_t ga0 = (size_t)(bm + l_r0) * K + k0 + l_c8 * 8;
        size_t gb0 = (size_t)(cn + l_r0) * K + k0 + l_c8 * 8;
        size_t ga1 = ga0 + (size_t)64 * K;
        size_t gb1 = gb0 + (size_t)64 * K;
        cpasync16(s0 + 0 * BUF_BYTES + so0, Ah + ga0);
        cpasync16(s0 + 1 * BUF_BYTES + so0, Al + ga0);
        cpasync16(s0 + 2 * BUF_BYTES + so0, Bp + gb0);
        cpasync16(s0 + 0 * BUF_BYTES + so1, Ah + ga1);
        cpasync16(s0 + 1 * BUF_BYTES + so1, Al + ga1);
        cpasync16(s0 + 2 * BUF_BYTES + so1, Bp + gb1);
    };

    // prologue: stages 0 and 1 in flight
    load_stage(0, 0);
    CP_COMMIT();
    load_stage(1, 32);        // nch >= 8 always
    CP_COMMIT();

    int st_c = 0;             // compute stage
    int st_l = 2;             // next load stage

    for (int c = 0; c < nch; c++) {
        if (c + 1 < nch) CP_WAIT1(); else CP_WAIT0();
        __syncthreads();

        if (c + 2 < nch) {
            load_stage(st_l, (c + 2) << 5);
            CP_COMMIT();
            if (++st_l == NSTG) st_l = 0;
        }

        const uint32_t s0  = sb + st_c * STG_BYTES;
        const uint32_t aAh = s0;
        const uint32_t aAl = s0 + 1 * BUF_BYTES;
        const uint32_t aB  = s0 + 2 * BUF_BYTES;

        #pragma unroll
        for (int s = 0; s < 2; s++) {
            const int akoff = s * 32 + a_kb;   // bytes within 80B row
            const int bkoff = s * 32 + b_kb;
            uint32_t bh[2][4];
            #pragma unroll
            for (int nb = 0; nb < 2; nb++) {
                uint32_t boffs = (uint32_t)(n_warp + nb * 16 + b_row) * (SP * 2) + bkoff;
                ldsm4(bh[nb][0], bh[nb][1], bh[nb][2], bh[nb][3], aB + boffs);
            }
            #pragma unroll
            for (int mi = 0; mi < 4; mi++) {
                uint32_t off = (uint32_t)(m_warp + mi * 16 + a_row) * (SP * 2) + akoff;
                uint32_t ah[4], al[4];
                ldsm4(ah[0], ah[1], ah[2], ah[3], aAh + off);
                ldsm4(al[0], al[1], al[2], al[3], aAl + off);
                #pragma unroll
                for (int nb = 0; nb < 2; nb++)
                    #pragma unroll
                    for (int nj = 0; nj < 2; nj++) {
                        float* d = acc[mi][nb * 2 + nj];
                        mma16816(d, ah, bh[nb][2 * nj], bh[nb][2 * nj + 1]);
                        mma16816(d, al, bh[nb][2 * nj], bh[nb][2 * nj + 1]);
                    }
            }
        }
        if (++st_c == NSTG) st_c = 0;
    }

    // epilogue: c0,c1 -> (row, col), c2,c3 -> (row+8, col)
    const bool isRoot = (cn >= NR * DH);
    const int rel = cn >> 8;
    const int cb128 = cn & 255;
    #pragma unroll
    for (int mi = 0; mi < 4; mi++) {
        int r0 = bm + m_warp + mi * 16 + (lane >> 2);
        #pragma unroll
        for (int half = 0; half < 2; half++) {
            int r = r0 + half * 8;
            if (r >= NN) continue;
            #pragma unroll
            for (int nj = 0; nj < 4; nj++) {
                int c = n_warp + nj * 8 + (lane & 3) * 2;
                float v0 = acc[mi][nj][half * 2 + 0];
                float v1 = acc[mi][nj][half * 2 + 1];
                if (isRoot) {
                    int col = (cn - NR * DH) + c;
                    float2 o = make_float2(v0 + bias[col], v1 + bias[col + 1]);
                    *(float2*)(g_acc + (size_t)r * DH + col) = o;
                } else {
                    *(float2*)(g_y + ((size_t)rel * NN + r) * DH + cb128 + c) = make_float2(v0, v1);
                }
            }
        }
    }
}

// ---------------- edge scatter: acc[dst] += y[rel][src] * invcnt[rel][dst] ----------------
__global__ __launch_bounds__(256) void edge_scatter() {
    int e = blockIdx.x * 8 + (threadIdx.x >> 5);
    if (e >= NE) return;
    int lane = threadIdx.x & 31;
    int src = g_src[e];
    int dst = g_dst[e];
    int rel = g_rel[e];
    float inv = g_invcnt[rel * NN + dst];
    const float4* ys = (const float4*)(g_y + ((size_t)rel * NN + src) * DH);
    float* ad = g_acc + (size_t)dst * DH;
    #pragma unroll
    for (int i = 0; i < 2; i++) {
        float4 v = ys[lane + 32 * i];
        red4(ad + (lane + 32 * i) * 4, v.x * inv, v.y * inv, v.z * inv, v.w * inv);
    }
}

// ---------------- relu + fp16 split for next layer (8 elems/thread) ----------------
__global__ void relu_bf_kernel(int writeF32) {
    int i = blockIdx.x * blockDim.x + threadIdx.x;
    if (i >= NN * DH / 8) return;
    const float4* p = (const float4*)g_acc + (size_t)i * 2;
    float4 v0 = p[0], v1 = p[1];
    float vv[8] = {v0.x, v0.y, v0.z, v0.w, v1.x, v1.y, v1.z, v1.w};
    union { __half b[8]; uint4 u; } H, L;
    #pragma unroll
    for (int j = 0; j < 8; j++) {
        vv[j] = fmaxf(vv[j], 0.f);
        split_fp16(vv[j], H.b[j], L.b[j]);
    }
    ((uint4*)g_hbh)[i] = H.u;
    ((uint4*)g_hbl)[i] = L.u;
    if (writeF32) {
        float4* q = (float4*)g_h + (size_t)i * 2;
        q[0] = make_float4(vv[0], vv[1], vv[2], vv[3]);
        q[1] = make_float4(vv[4], vv[5], vv[6], vv[7]);
    }
}

// ---------------- graph pooling (sum + max + count) ----------------
__global__ void pool_kernel() {
    int idx = blockIdx.x * blockDim.x + threadIdx.x;
    if (idx >= NN * DH) return;
    int node = idx >> 8;
    int d    = idx & (DH - 1);
    int g    = g_bat[node];
    float v  = g_h[idx];
    atomicAdd(&g_psum[g * DH + d], v);
    atomicMax(&g_pmax[g * DH + d], __float_as_int(v));
    if (d == 0) atomicAdd(&g_gcnt[g], 1.f);
}

// ---------------- final MLP head ----------------
__global__ __launch_bounds__(128) void mlp_kernel(
    const float* __restrict__ fc1w, const float* __restrict__ fc1b,
    const float* __restrict__ fc2w, const float* __restrict__ fc2b,
    float* __restrict__ out)
{
    __shared__ float gv[2 * DH];
    __shared__ float partial[4];
    int gi = blockIdx.x;
    int t  = threadIdx.x;
    float cnt = fmaxf(g_gcnt[gi], 1.f);
    for (int i = t; i < DH; i += 128) {
        gv[i]      = g_psum[gi * DH + i] / cnt;
        gv[DH + i] = __int_as_float(g_pmax[gi * DH + i]);
    }
    __syncthreads();
    float a = fc1b[t];
    #pragma unroll 8
    for (int i = 0; i < 2 * DH; i++) a += gv[i] * fc1w[i * 128 + t];
    a = fmaxf(a, 0.f);
    float p = a * fc2w[t];
    #pragma unroll
    for (int o = 16; o > 0; o >>= 1) p += __shfl_down_sync(0xffffffffu, p, o);
    if ((t & 31) == 0) partial[t >> 5] = p;
    __syncthreads();
    if (t == 0) {
        float s = partial[0] + partial[1] + partial[2] + partial[3] + fc2b[0];
        out[gi] = 1.f / (1.f + expf(-s));
    }
}

// ---------------- launch ----------------
extern "C" void kernel_launch(void* const* d_in, const int* in_sizes, int n_in,
                              void* d_out, int out_size)
{
    const float* x         = (const float*)d_in[0];
    const void*  ei        = d_in[1];
    const void*  ea        = d_in[2];
    const void*  ba        = d_in[3];
    const float* w0        = (const float*)d_in[4];
    const float* root0     = (const float*)d_in[5];
    const float* b0        = (const float*)d_in[6];
    const float* w_rest    = (const float*)d_in[7];
    const float* root_rest = (const float*)d_in[8];
    const float* b_rest    = (const float*)d_in[9];
    const float* fc1w      = (const float*)d_in[10];
    const float* fc1b      = (const float*)d_in[11];
    const float* fc2w      = (const float*)d_in[12];
    const float* fc2b      = (const float*)d_in[13];
    float* out = (float*)d_out;

    const int T = 256;

    cudaFuncSetAttribute(gemm_mma, cudaFuncAttributeMaxDynamicSharedMemorySize, GSMEM_TOTAL);

    dim3 ggrid((NN + 127) / 128, 10);
    const int egrid = (NE + 7) / 8;
    const int rgrid8 = (NN * DH / 8 + T - 1) / T;

    // conversions first so gemm_mma(layer 0) is the 4th launch (ncu -s 5 target)
    cvt_x_kernel<<<(NN * DIN / 8 + T - 1) / T, T>>>(x);
    cvt_w0_kernel<<<(W0_ELEMS + T - 1) / T, T>>>(w0, root0);
    cvt_wrest_kernel<<<(5 * WR_ELEMS + T - 1) / T, T>>>(w_rest, root_rest);

    gemm_mma<<<ggrid, 256, GSMEM_TOTAL>>>(0, b0);   // layer 0 GEMM (profiled launch)

    // index decode + normalizers (needed before first edge_scatter)
    detect_kernel<<<1, 256>>>((const unsigned*)ei, (const unsigned*)ea, (const unsigned*)ba);
    cvt_edges_kernel<<<(NE + T - 1) / T, T>>>(ei, ea);
    cvt_batch_kernel<<<(NN + T - 1) / T, T>>>(ba);
    zero_cnt_kernel<<<(NR * NN + T - 1) / T, T>>>();
    count_edges_kernel<<<(NE + T - 1) / T, T>>>();
    make_inv_kernel<<<(NR * NN + T - 1) / T, T>>>();

    edge_scatter<<<egrid, 256>>>();
    relu_bf_kernel<<<rgrid8, T>>>(0);

    for (int l = 1; l < NL; l++) {
        gemm_mma<<<ggrid, 256, GSMEM_TOTAL>>>(l, b_rest + (size_t)(l - 1) * DH);
        edge_scatter<<<egrid, 256>>>();
        relu_bf_kernel<<<rgrid8, T>>>(l == NL - 1 ? 1 : 0);
    }

    zero_pool_kernel<<<(NG * DH + T - 1) / T, T>>>();
    pool_kernel<<<(NN * DH + T - 1) / T, T>>>();
    mlp_kernel<<<NG, 128>>>(fc1w, fc1b, fc2w, fc2b, out);
}

// round 16
// speedup vs baseline: 3.2233x; 1.0009x over previous
#include <cuda_runtime.h>
#include <cuda_fp16.h>
#include <math.h>
#include <stdint.h>

#define NN 60000
#define NNP 60128          // padded rows (tile overrun safe)
#define NE 240000
#define NR 4
#define NG 128
#define DIN 768
#define DH 256
#define NL 6

// ---------------- scratch (static device globals; no allocation) ----------------
__device__ __align__(16) float g_h[(size_t)NN * DH];          // fp32 activations (for pooling)
__device__ __align__(16) float g_acc[(size_t)NN * DH];        // root transform + edge accumulation
__device__ __align__(16) float g_y[(size_t)NR * NN * DH];     // per-relation transformed features
__device__ __align__(16) float g_cnt[NR * NN];
__device__ __align__(16) float g_invcnt[NR * NN];
__device__ __align__(16) float g_psum[NG * DH];
__device__ __align__(16) int   g_pmax[NG * DH];
__device__ __align__(16) float g_gcnt[NG];

// fp16 hi/lo split activations for tensor-core GEMMs (A side exact to ~22 bits)
__device__ __align__(16) __half g_xh[(size_t)NNP * DIN];
__device__ __align__(16) __half g_xl[(size_t)NNP * DIN];
__device__ __align__(16) __half g_hbh[(size_t)NNP * DH];
__device__ __align__(16) __half g_hbl[(size_t)NNP * DH];
// transposed weights (single fp16): layer0 [1280][768] then layers1-5 [1280][256]
#define W0_ELEMS (1280 * 768)
#define WR_ELEMS (1280 * 256)
#define WT_TOTAL (W0_ELEMS + 5 * WR_ELEMS)
__device__ __align__(16) __half g_wt[WT_TOTAL];

// decoded int32 index arrays + dtype flags
__device__ int g_src[NE];
__device__ int g_dst[NE];
__device__ int g_rel[NE];
__device__ int g_bat[NN];
__device__ int g_is64_ei, g_is64_ea, g_is64_b;

// ---------------- helpers ----------------
__device__ __forceinline__ uint32_t smem_to_u32(const void* p) {
    uint32_t a;
    asm("{ .reg .u64 t; cvta.to.shared.u64 t, %1; cvt.u32.u64 %0, t; }" : "=r"(a) : "l"(p));
    return a;
}

__device__ __forceinline__ void ldsm4(uint32_t& r0, uint32_t& r1, uint32_t& r2, uint32_t& r3, uint32_t addr) {
    asm volatile("ldmatrix.sync.aligned.m8n8.x4.shared.b16 {%0,%1,%2,%3}, [%4];"
                 : "=r"(r0), "=r"(r1), "=r"(r2), "=r"(r3) : "r"(addr));
}

__device__ __forceinline__ void mma16816(float* d, const uint32_t* a, uint32_t b0, uint32_t b1) {
    asm volatile("mma.sync.aligned.m16n8k16.row.col.f32.f16.f16.f32 "
                 "{%0,%1,%2,%3}, {%4,%5,%6,%7}, {%8,%9}, {%0,%1,%2,%3};"
                 : "+f"(d[0]), "+f"(d[1]), "+f"(d[2]), "+f"(d[3])
                 : "r"(a[0]), "r"(a[1]), "r"(a[2]), "r"(a[3]), "r"(b0), "r"(b1));
}

__device__ __forceinline__ void cpasync16(uint32_t saddr, const void* gaddr) {
    asm volatile("cp.async.cg.shared.global [%0], [%1], 16;" :: "r"(saddr), "l"(gaddr));
}
#define CP_COMMIT() asm volatile("cp.async.commit_group;" ::: "memory")
#define CP_WAIT0()  asm volatile("cp.async.wait_group 0;" ::: "memory")
#define CP_WAIT1()  asm volatile("cp.async.wait_group 1;" ::: "memory")

__device__ __forceinline__ void red4(float* p, float a, float b, float c, float d) {
    asm volatile("red.global.add.v4.f32 [%0], {%1,%2,%3,%4};"
                 :: "l"(p), "f"(a), "f"(b), "f"(c), "f"(d) : "memory");
}

__device__ __forceinline__ void split_fp16(float v, __half& hi, __half& lo) {
    hi = __float2half(v);
    lo = __float2half(v - __half2float(hi));
}

// ---------------- dtype detection ----------------
__global__ void detect_kernel(const unsigned* __restrict__ ei,
                              const unsigned* __restrict__ ea,
                              const unsigned* __restrict__ ba) {
    __shared__ int s[3];
    int t = threadIdx.x;
    if (t < 3) s[t] = 1;
    __syncthreads();
    { unsigned w = ei[2 * (t * 937) + 1]; if (w != 0) atomicAnd(&s[0], 0); }
    { unsigned w = ea[2 * (t * 468) + 1]; if (w != 0) atomicAnd(&s[1], 0); }
    { unsigned w = ba[2 * (t * 117) + 1]; if (w != 0) atomicAnd(&s[2], 0); }
    __syncthreads();
    if (t == 0) { g_is64_ei = s[0]; g_is64_ea = s[1]; g_is64_b = s[2]; }
}

__global__ void cvt_edges_kernel(const void* __restrict__ ei, const void* __restrict__ ea) {
    int e = blockIdx.x * blockDim.x + threadIdx.x;
    if (e >= NE) return;
    long long s, d, r;
    if (g_is64_ei) { const long long* p = (const long long*)ei; s = p[e]; d = p[NE + e]; }
    else           { const int* p = (const int*)ei;             s = p[e]; d = p[NE + e]; }
    if (g_is64_ea) r = ((const long long*)ea)[e];
    else           r = ((const int*)ea)[e];
    g_src[e] = (int)(s < 0 ? 0 : (s >= NN ? NN - 1 : s));
    g_dst[e] = (int)(d < 0 ? 0 : (d >= NN ? NN - 1 : d));
    g_rel[e] = (int)(r & 3);
}

__global__ void cvt_batch_kernel(const void* __restrict__ ba) {
    int i = blockIdx.x * blockDim.x + threadIdx.x;
    if (i >= NN) return;
    long long b = g_is64_b ? ((const long long*)ba)[i] : (long long)((const int*)ba)[i];
    g_bat[i] = (int)(b < 0 ? 0 : (b >= NG ? NG - 1 : b));
}

// ---------------- fp16 hi/lo conversions (vectorized: 8 elems/thread) ----------------
__global__ void cvt_x_kernel(const float* __restrict__ x) {
    int i = blockIdx.x * blockDim.x + threadIdx.x;
    if (i >= NN * DIN / 8) return;
    const float4* p = (const float4*)x + (size_t)i * 2;
    float4 v0 = p[0], v1 = p[1];
    float vv[8] = {v0.x, v0.y, v0.z, v0.w, v1.x, v1.y, v1.z, v1.w};
    union { __half b[8]; uint4 u; } H, L;
    #pragma unroll
    for (int j = 0; j < 8; j++) split_fp16(vv[j], H.b[j], L.b[j]);
    ((uint4*)g_xh)[i] = H.u;
    ((uint4*)g_xl)[i] = L.u;
}

// layer0 weights transposed: g_wt[n][k], n in [0,1280), k in [0,768)
__global__ void cvt_w0_kernel(const float* __restrict__ w0, const float* __restrict__ root0) {
    int i = blockIdx.x * blockDim.x + threadIdx.x;
    if (i >= W0_ELEMS) return;
    int n = i / DIN, k = i - n * DIN;
    float v = (n < NR * DH) ? w0[((size_t)(n >> 8) * DIN + k) * DH + (n & 255)]
                            : root0[(size_t)k * DH + (n - NR * DH)];
    g_wt[i] = __float2half(v);
}

// layers 1..5: g_wt[W0 + l5*WR + n*256 + k]
__global__ void cvt_wrest_kernel(const float* __restrict__ w_rest, const float* __restrict__ root_rest) {
    int i = blockIdx.x * blockDim.x + threadIdx.x;
    if (i >= 5 * WR_ELEMS) return;
    int l5 = i / WR_ELEMS;
    int rem = i - l5 * WR_ELEMS;
    int n = rem >> 8, k = rem & 255;
    float v = (n < NR * DH)
        ? w_rest[(((size_t)l5 * NR + (n >> 8)) * DH + k) * DH + (n & 255)]
        : root_rest[((size_t)l5 * DH + k) * DH + (n - NR * DH)];
    g_wt[W0_ELEMS + i] = __float2half(v);
}

// ---------------- small utility kernels ----------------
__global__ void zero_cnt_kernel() {
    int i = blockIdx.x * blockDim.x + threadIdx.x;
    if (i < NR * NN) g_cnt[i] = 0.f;
}
__global__ void count_edges_kernel() {
    int e = blockIdx.x * blockDim.x + threadIdx.x;
    if (e >= NE) return;
    atomicAdd(&g_cnt[g_rel[e] * NN + g_dst[e]], 1.f);
}
__global__ void make_inv_kernel() {
    int i = blockIdx.x * blockDim.x + threadIdx.x;
    if (i < NR * NN) g_invcnt[i] = 1.f / fmaxf(g_cnt[i], 1.f);
}
__global__ void zero_pool_kernel() {
    int i = blockIdx.x * blockDim.x + threadIdx.x;
    if (i < NG * DH) { g_psum[i] = 0.f; g_pmax[i] = 0; }
    if (i < NG) g_gcnt[i] = 0.f;
}

// ---------------- mma.sync GEMM, 3-stage cp.async pipeline, fp16 2-pass ----------------
// C[60000 x 1280] = A[60000 x K] @ [W0|W1|W2|W3|root]^T.
// A = Ah + Al (fp16 split); B single fp16. Block tile 128x128x32, 8 warps.
// GRID: blockIdx.x = cn (10 col-blocks), blockIdx.y = m (469 row-blocks) so a
// resident wave shares each A tile across all 10 col-blocks (10x L2 reuse of A).
#define SP 40
#define BUF_BYTES (128 * SP * 2)          // 10240 per buffer
#define STG_BYTES (3 * BUF_BYTES)         // Ah, Al, B = 30720 per stage
#define NSTG 3
#define GSMEM_TOTAL (NSTG * STG_BYTES)    // 92160

__global__ __launch_bounds__(256, 2) void gemm_mma(int layer, const float* __restrict__ bias)
{
    extern __shared__ char dsm[];
    const uint32_t sb = smem_to_u32(dsm);

    const int K = layer ? DH : DIN;
    const size_t boff = layer ? (size_t)W0_ELEMS + (size_t)(layer - 1) * WR_ELEMS : 0;
    const __half* __restrict__ Ah = layer ? (const __half*)g_hbh : (const __half*)g_xh;
    const __half* __restrict__ Al = layer ? (const __half*)g_hbl : (const __half*)g_xl;
    const __half* __restrict__ Bp = (const __half*)g_wt + boff;

    const int bm = blockIdx.y * 128;       // m tile (slow dim)
    const int cn = blockIdx.x * 128;       // col tile (fast dim -> wave covers all 10)

    const int tid = threadIdx.x, lane = tid & 31, wid = tid >> 5;
    const int m_warp = (wid >> 2) * 64, n_warp = (wid & 3) * 32;

    float acc[4][4][4] = {};

    // per-thread load coords (6 x cp.async of 16B per stage: 2 row-halves x 3 buffers)
    const int l_r0 = tid >> 2;            // 0..63
    const int l_c8 = tid & 3;             // 16B chunk within 64B row-chunk
    const uint32_t so0 = (uint32_t)(l_r0 * SP + l_c8 * 8) * 2;
    const uint32_t so1 = (uint32_t)((l_r0 + 64) * SP + l_c8 * 8) * 2;

    // ldmatrix per-lane address components
    const int a_row = lane & 15;
    const int a_kb  = (lane >> 4) << 4;
    const int bg    = lane >> 3;
    const int b_row = ((bg & 2) << 2) + (lane & 7);
    const int b_kb  = (bg & 1) << 4;

    const int nch = K >> 5;

    auto load_stage = [&](int st, int k0) {
        const uint32_t s0 = sb + st * STG_BYTES;
        size_t ga0 = (size_t)(bm + l_r0) * K + k0 + l_c8 * 8;
        size_t gb0 = (size_t)(cn + l_r0) * K + k0 + l_c8 * 8;
        size_t ga1 = ga0 + (size_t)64 * K;
        size_t gb1 = gb0 + (size_t)64 * K;
        cpasync16(s0 + 0 * BUF_BYTES + so0, Ah + ga0);
        cpasync16(s0 + 1 * BUF_BYTES + so0, Al + ga0);
        cpasync16(s0 + 2 * BUF_BYTES + so0, Bp + gb0);
        cpasync16(s0 + 0 * BUF_BYTES + so1, Ah + ga1);
        cpasync16(s0 + 1 * BUF_BYTES + so1, Al + ga1);
        cpasync16(s0 + 2 * BUF_BYTES + so1, Bp + gb1);
    };

    // prologue: stages 0 and 1 in flight
    load_stage(0, 0);
    CP_COMMIT();
    load_stage(1, 32);        // nch >= 8 always
    CP_COMMIT();

    int st_c = 0;             // compute stage
    int st_l = 2;             // next load stage

    for (int c = 0; c < nch; c++) {
        if (c + 1 < nch) CP_WAIT1(); else CP_WAIT0();
        __syncthreads();

        if (c + 2 < nch) {
            load_stage(st_l, (c + 2) << 5);
            CP_COMMIT();
            if (++st_l == NSTG) st_l = 0;
        }

        const uint32_t s0  = sb + st_c * STG_BYTES;
        const uint32_t aAh = s0;
        const uint32_t aAl = s0 + 1 * BUF_BYTES;
        const uint32_t aB  = s0 + 2 * BUF_BYTES;

        #pragma unroll
        for (int s = 0; s < 2; s++) {
            const int akoff = s * 32 + a_kb;   // bytes within 80B row
            const int bkoff = s * 32 + b_kb;
            uint32_t bh[2][4];
            #pragma unroll
            for (int nb = 0; nb < 2; nb++) {
                uint32_t boffs = (uint32_t)(n_warp + nb * 16 + b_row) * (SP * 2) + bkoff;
                ldsm4(bh[nb][0], bh[nb][1], bh[nb][2], bh[nb][3], aB + boffs);
            }
            #pragma unroll
            for (int mi = 0; mi < 4; mi++) {
                uint32_t off = (uint32_t)(m_warp + mi * 16 + a_row) * (SP * 2) + akoff;
                uint32_t ah[4], al[4];
                ldsm4(ah[0], ah[1], ah[2], ah[3], aAh + off);
                ldsm4(al[0], al[1], al[2], al[3], aAl + off);
                #pragma unroll
                for (int nb = 0; nb < 2; nb++)
                    #pragma unroll
                    for (int nj = 0; nj < 2; nj++) {
                        float* d = acc[mi][nb * 2 + nj];
                        mma16816(d, ah, bh[nb][2 * nj], bh[nb][2 * nj + 1]);
                        mma16816(d, al, bh[nb][2 * nj], bh[nb][2 * nj + 1]);
                    }
            }
        }
        if (++st_c == NSTG) st_c = 0;
    }

    // epilogue: c0,c1 -> (row, col), c2,c3 -> (row+8, col)
    const bool isRoot = (cn >= NR * DH);
    const int rel = cn >> 8;
    const int cb128 = cn & 255;
    #pragma unroll
    for (int mi = 0; mi < 4; mi++) {
        int r0 = bm + m_warp + mi * 16 + (lane >> 2);
        #pragma unroll
        for (int half = 0; half < 2; half++) {
            int r = r0 + half * 8;
            if (r >= NN) continue;
            #pragma unroll
            for (int nj = 0; nj < 4; nj++) {
                int c = n_warp + nj * 8 + (lane & 3) * 2;
                float v0 = acc[mi][nj][half * 2 + 0];
                float v1 = acc[mi][nj][half * 2 + 1];
                if (isRoot) {
                    int col = (cn - NR * DH) + c;
                    float2 o = make_float2(v0 + bias[col], v1 + bias[col + 1]);
                    *(float2*)(g_acc + (size_t)r * DH + col) = o;
                } else {
                    *(float2*)(g_y + ((size_t)rel * NN + r) * DH + cb128 + c) = make_float2(v0, v1);
                }
            }
        }
    }
}

// ---------------- edge scatter: acc[dst] += y[rel][src] * invcnt[rel][dst] ----------------
__global__ __launch_bounds__(256) void edge_scatter() {
    int e = blockIdx.x * 8 + (threadIdx.x >> 5);
    if (e >= NE) return;
    int lane = threadIdx.x & 31;
    int src = g_src[e];
    int dst = g_dst[e];
    int rel = g_rel[e];
    float inv = g_invcnt[rel * NN + dst];
    const float4* ys = (const float4*)(g_y + ((size_t)rel * NN + src) * DH);
    float* ad = g_acc + (size_t)dst * DH;
    #pragma unroll
    for (int i = 0; i < 2; i++) {
        float4 v = ys[lane + 32 * i];
        red4(ad + (lane + 32 * i) * 4, v.x * inv, v.y * inv, v.z * inv, v.w * inv);
    }
}

// ---------------- relu + fp16 split for next layer (8 elems/thread) ----------------
__global__ void relu_bf_kernel(int writeF32) {
    int i = blockIdx.x * blockDim.x + threadIdx.x;
    if (i >= NN * DH / 8) return;
    const float4* p = (const float4*)g_acc + (size_t)i * 2;
    float4 v0 = p[0], v1 = p[1];
    float vv[8] = {v0.x, v0.y, v0.z, v0.w, v1.x, v1.y, v1.z, v1.w};
    union { __half b[8]; uint4 u; } H, L;
    #pragma unroll
    for (int j = 0; j < 8; j++) {
        vv[j] = fmaxf(vv[j], 0.f);
        split_fp16(vv[j], H.b[j], L.b[j]);
    }
    ((uint4*)g_hbh)[i] = H.u;
    ((uint4*)g_hbl)[i] = L.u;
    if (writeF32) {
        float4* q = (float4*)g_h + (size_t)i * 2;
        q[0] = make_float4(vv[0], vv[1], vv[2], vv[3]);
        q[1] = make_float4(vv[4], vv[5], vv[6], vv[7]);
    }
}

// ---------------- graph pooling (sum + max + count) ----------------
__global__ void pool_kernel() {
    int idx = blockIdx.x * blockDim.x + threadIdx.x;
    if (idx >= NN * DH) return;
    int node = idx >> 8;
    int d    = idx & (DH - 1);
    int g    = g_bat[node];
    float v  = g_h[idx];
    atomicAdd(&g_psum[g * DH + d], v);
    atomicMax(&g_pmax[g * DH + d], __float_as_int(v));
    if (d == 0) atomicAdd(&g_gcnt[g], 1.f);
}

// ---------------- final MLP head ----------------
__global__ __launch_bounds__(128) void mlp_kernel(
    const float* __restrict__ fc1w, const float* __restrict__ fc1b,
    const float* __restrict__ fc2w, const float* __restrict__ fc2b,
    float* __restrict__ out)
{
    __shared__ float gv[2 * DH];
    __shared__ float partial[4];
    int gi = blockIdx.x;
    int t  = threadIdx.x;
    float cnt = fmaxf(g_gcnt[gi], 1.f);
    for (int i = t; i < DH; i += 128) {
        gv[i]      = g_psum[gi * DH + i] / cnt;
        gv[DH + i] = __int_as_float(g_pmax[gi * DH + i]);
    }
    __syncthreads();
    float a = fc1b[t];
    #pragma unroll 8
    for (int i = 0; i < 2 * DH; i++) a += gv[i] * fc1w[i * 128 + t];
    a = fmaxf(a, 0.f);
    float p = a * fc2w[t];
    #pragma unroll
    for (int o = 16; o > 0; o >>= 1) p += __shfl_down_sync(0xffffffffu, p, o);
    if ((t & 31) == 0) partial[t >> 5] = p;
    __syncthreads();
    if (t == 0) {
        float s = partial[0] + partial[1] + partial[2] + partial[3] + fc2b[0];
        out[gi] = 1.f / (1.f + expf(-s));
    }
}

// ---------------- launch ----------------
extern "C" void kernel_launch(void* const* d_in, const int* in_sizes, int n_in,
                              void* d_out, int out_size)
{
    const float* x         = (const float*)d_in[0];
    const void*  ei        = d_in[1];
    const void*  ea        = d_in[2];
    const void*  ba        = d_in[3];
    const float* w0        = (const float*)d_in[4];
    const float* root0     = (const float*)d_in[5];
    const float* b0        = (const float*)d_in[6];
    const float* w_rest    = (const float*)d_in[7];
    const float* root_rest = (const float*)d_in[8];
    const float* b_rest    = (const float*)d_in[9];
    const float* fc1w      = (const float*)d_in[10];
    const float* fc1b      = (const float*)d_in[11];
    const float* fc2w      = (const float*)d_in[12];
    const float* fc2b      = (const float*)d_in[13];
    float* out = (float*)d_out;

    const int T = 256;

    cudaFuncSetAttribute(gemm_mma, cudaFuncAttributeMaxDynamicSharedMemorySize, GSMEM_TOTAL);

    dim3 ggrid(10, (NN + 127) / 128);   // x = col-blocks (fast), y = m-blocks
    const int egrid = (NE + 7) / 8;
    const int rgrid8 = (NN * DH / 8 + T - 1) / T;

    // conversions first so gemm_mma(layer 0) is the 4th launch (ncu -s 5 target)
    cvt_x_kernel<<<(NN * DIN / 8 + T - 1) / T, T>>>(x);
    cvt_w0_kernel<<<(W0_ELEMS + T - 1) / T, T>>>(w0, root0);
    cvt_wrest_kernel<<<(5 * WR_ELEMS + T - 1) / T, T>>>(w_rest, root_rest);

    gemm_mma<<<ggrid, 256, GSMEM_TOTAL>>>(0, b0);   // layer 0 GEMM (profiled launch)

    // index decode + normalizers (needed before first edge_scatter)
    detect_kernel<<<1, 256>>>((const unsigned*)ei, (const unsigned*)ea, (const unsigned*)ba);
    cvt_edges_kernel<<<(NE + T - 1) / T, T>>>(ei, ea);
    cvt_batch_kernel<<<(NN + T - 1) / T, T>>>(ba);
    zero_cnt_kernel<<<(NR * NN + T - 1) / T, T>>>();
    count_edges_kernel<<<(NE + T - 1) / T, T>>>();
    make_inv_kernel<<<(NR * NN + T - 1) / T, T>>>();

    edge_scatter<<<egrid, 256>>>();
    relu_bf_kernel<<<rgrid8, T>>>(0);

    for (int l = 1; l < NL; l++) {
        gemm_mma<<<ggrid, 256, GSMEM_TOTAL>>>(l, b_rest + (size_t)(l - 1) * DH);
        edge_scatter<<<egrid, 256>>>();
        relu_bf_kernel<<<rgrid8, T>>>(l == NL - 1 ? 1 : 0);
    }

    zero_pool_kernel<<<(NG * DH + T - 1) / T, T>>>();
    pool_kernel<<<(NN * DH + T - 1) / T, T>>>();
    mlp_kernel<<<NG, 128>>>(fc1w, fc1b, fc2w, fc2b, out);
}